// round 8
// baseline (speedup 1.0000x reference)
#include <cuda_runtime.h>
#include <cstdint>

#define BTOT   500000
#define NDIM   3
#define NCOND  64
#define NHID   128
#define NIN    68      // NDIM + NCOND + 1
#define TILE   64
#define NT     256

typedef unsigned long long ull;

// Transposed hidden-layer weights for backward pass.
__device__ float g_Wt1[NHID * NHID];
__device__ float g_Wt2[NHID * NHID];

__global__ void transpose_k(const float* __restrict__ W1, const float* __restrict__ W2) {
    int idx = blockIdx.x * blockDim.x + threadIdx.x;
    if (idx < NHID * NHID) {
        int r = idx >> 7, c = idx & 127;
        g_Wt1[c * NHID + r] = W1[idx];
        g_Wt2[c * NHID + r] = W2[idx];
    }
}

__device__ __forceinline__ float ftanh(float x) {
    float e = __expf(2.0f * x);
    return __fdividef(e - 1.0f, e + 1.0f);
}

__device__ __forceinline__ ull pk(float lo, float hi) {
    ull r; asm("mov.b64 %0, {%1,%2};" : "=l"(r) : "f"(lo), "f"(hi)); return r;
}
__device__ __forceinline__ void upk(ull v, float& lo, float& hi) {
    asm("mov.b64 {%0,%1}, %2;" : "=f"(lo), "=f"(hi) : "l"(v));
}
__device__ __forceinline__ void fma2(ull& d, ull a, ull b) {
    asm("fma.rn.f32x2 %0, %1, %2, %3;" : "=l"(d) : "l"(a), "l"(b), "l"(d));
}

// acc[u][cp]: rows (r2+u), col-pair (j0+2cp, j0+2cp+1).
// sA: [K][TILE] transposed activations in SMEM; gW: [K][NHID] row-major in GMEM.
// A load: conflict-free LDS.64. W loads: 4x LDG.128, warp-uniform address
// (L1/L2 broadcast), consumed directly as packed f32 pairs.
template<int K>
__device__ __forceinline__ void mmf2g(const float* __restrict__ sA,
                                      const float* __restrict__ gW,
                                      int r2, int j0, ull acc[2][8]) {
#pragma unroll
    for (int u = 0; u < 2; u++)
#pragma unroll
        for (int c = 0; c < 8; c++) acc[u][c] = 0ULL;

#pragma unroll 4
    for (int k = 0; k < K; k++) {
        float2 a = *reinterpret_cast<const float2*>(sA + k * TILE + r2);
        ull a0 = pk(a.x, a.x);
        ull a1 = pk(a.y, a.y);
        const ulonglong2* wp = reinterpret_cast<const ulonglong2*>(gW + k * NHID + j0);
        ulonglong2 q0 = __ldg(wp + 0);
        ulonglong2 q1 = __ldg(wp + 1);
        ulonglong2 q2 = __ldg(wp + 2);
        ulonglong2 q3 = __ldg(wp + 3);
        ull w[8] = {q0.x, q0.y, q1.x, q1.y, q2.x, q2.y, q3.x, q3.y};
#pragma unroll
        for (int c = 0; c < 8; c++) { fma2(acc[0][c], a0, w[c]); fma2(acc[1][c], a1, w[c]); }
    }
}

__device__ __forceinline__ void epi_tanh(ull acc[2][8], const float* __restrict__ bias,
                                         float* __restrict__ sH, int r2, int j0) {
#pragma unroll
    for (int c = 0; c < 8; c++) {
        int j = j0 + 2 * c;
        float b0 = __ldg(bias + j), b1 = __ldg(bias + j + 1);
        float x00, x01, x10, x11;
        upk(acc[0][c], x00, x01);
        upk(acc[1][c], x10, x11);
        *reinterpret_cast<float2*>(sH + j * TILE + r2) =
            make_float2(ftanh(x00 + b0), ftanh(x10 + b0));
        *reinterpret_cast<float2*>(sH + (j + 1) * TILE + r2) =
            make_float2(ftanh(x01 + b1), ftanh(x11 + b1));
    }
}

// dst = acc * (1 - h^2); h read from sHprev at same slots (per-thread owned).
__device__ __forceinline__ void epi_bwd(ull acc[2][8], const float* __restrict__ sHprev,
                                        float* __restrict__ sDst, int r2, int j0) {
#pragma unroll
    for (int c = 0; c < 8; c++) {
        int j = j0 + 2 * c;
        float x00, x01, x10, x11;
        upk(acc[0][c], x00, x01);
        upk(acc[1][c], x10, x11);
        float2 h0 = *reinterpret_cast<const float2*>(sHprev + j * TILE + r2);
        float2 h1 = *reinterpret_cast<const float2*>(sHprev + (j + 1) * TILE + r2);
        *reinterpret_cast<float2*>(sDst + j * TILE + r2) =
            make_float2(x00 * (1.0f - h0.x * h0.x), x10 * (1.0f - h0.y * h0.y));
        *reinterpret_cast<float2*>(sDst + (j + 1) * TILE + r2) =
            make_float2(x01 * (1.0f - h1.x * h1.x), x11 * (1.0f - h1.y * h1.y));
    }
}

// SMEM layout (floats):
//   sX   [8192] : sIn (first NIN*TILE=4352) during L1, then g3 buffer
//   sH1  [8192]
//   sH2  [8192]
//   sWout[384]  : W_out copy
//   sScr [1536] : f / gz reduction scratch
#define SM_X     0
#define SM_H1    8192
#define SM_H2    16384
#define SM_WOUT  24576
#define SM_SCR   24960
#define SM_TOTF  26496   // 105,984 bytes

__global__ __launch_bounds__(NT, 2)
void ode_kernel(const float* __restrict__ t_p,
                const float* __restrict__ z,
                const float* __restrict__ context,
                const float* __restrict__ eps,
                const float* __restrict__ W_in,  const float* __restrict__ b_in,
                const float* __restrict__ W_h1,  const float* __restrict__ b_h1,
                const float* __restrict__ W_h2,  const float* __restrict__ b_h2,
                const float* __restrict__ W_out, const float* __restrict__ b_out,
                const float* __restrict__ scale_p,
                float* __restrict__ out)
{
    extern __shared__ float sm[];
    float* sX    = sm + SM_X;
    float* sH1   = sm + SM_H1;
    float* sH2   = sm + SM_H2;
    float* sWout = sm + SM_WOUT;
    float* sScr  = sm + SM_SCR;

    const int t    = threadIdx.x;
    const int lane = t & 31;
    const int warp = t >> 5;
    const int j0   = warp * 16;
    const int r2   = lane * 2;
    const int row0 = blockIdx.x * TILE;
    const float tval   = *t_p;
    const float oscale = *scale_p;

    // ---- Stage input tile transposed sX[k][r]; W_out copy; eps to regs ----
    for (int idx = t; idx < NIN * TILE; idx += NT) {
        int k = idx >> 6, r = idx & 63;
        int grow = row0 + r;
        float v = 0.0f;
        if (grow < BTOT) {
            if (k < NDIM)              v = z[grow * NDIM + k];
            else if (k < NDIM + NCOND) v = context[grow * NCOND + (k - NDIM)];
            else                       v = tval;
        }
        sX[idx] = v;
    }
    for (int idx = t; idx < NHID * NDIM; idx += NT)   // FIX: strided (384 > 256)
        sWout[idx] = __ldg(W_out + idx);

    float ep[2][3];
    {
        int g0 = row0 + r2, g1r = row0 + r2 + 1;
#pragma unroll
        for (int d = 0; d < 3; d++) {
            ep[0][d] = (g0  < BTOT) ? __ldg(eps + g0  * NDIM + d) : 0.0f;
            ep[1][d] = (g1r < BTOT) ? __ldg(eps + g1r * NDIM + d) : 0.0f;
        }
    }
    __syncthreads();

    ull acc[2][8];

    // ---- L1: h1 = tanh(inp @ W_in + b_in) ----
    mmf2g<NIN>(sX, W_in, r2, j0, acc);
    epi_tanh(acc, b_in, sH1, r2, j0);
    __syncthreads();

    // ---- L2: h2 = tanh(h1 @ W_h1 + b_h1) ----
    mmf2g<NHID>(sH1, W_h1, r2, j0, acc);
    epi_tanh(acc, b_h1, sH2, r2, j0);
    __syncthreads();

    // ---- L3 + fused epilogue: h3 in regs; f partials; g3 -> sX ----
    mmf2g<NHID>(sH2, W_h2, r2, j0, acc);
    {
        float h[2][16];
#pragma unroll
        for (int c = 0; c < 8; c++) {
            int j = j0 + 2 * c;
            float b0 = __ldg(b_h2 + j), b1 = __ldg(b_h2 + j + 1);
            float x00, x01, x10, x11;
            upk(acc[0][c], x00, x01);
            upk(acc[1][c], x10, x11);
            h[0][2*c]   = ftanh(x00 + b0);
            h[0][2*c+1] = ftanh(x01 + b1);
            h[1][2*c]   = ftanh(x10 + b0);
            h[1][2*c+1] = ftanh(x11 + b1);
        }
        float pf[2][3] = {{0,0,0},{0,0,0}};
#pragma unroll
        for (int c = 0; c < 16; c++) {
            int j = j0 + c;
            float w0 = sWout[j * 3 + 0];
            float w1 = sWout[j * 3 + 1];
            float w2 = sWout[j * 3 + 2];
            float g3a, g3b;
#pragma unroll
            for (int u = 0; u < 2; u++) {
                float hv = h[u][c];
                pf[u][0] = fmaf(hv, w0, pf[u][0]);
                pf[u][1] = fmaf(hv, w1, pf[u][1]);
                pf[u][2] = fmaf(hv, w2, pf[u][2]);
                float s = ep[u][0] * w0 + ep[u][1] * w1 + ep[u][2] * w2;
                float g = s * oscale * (1.0f - hv * hv);
                if (u == 0) g3a = g; else g3b = g;
            }
            *reinterpret_cast<float2*>(sX + j * TILE + r2) = make_float2(g3a, g3b);
        }
        // f partials -> scratch: sScr[warp*192 + r*3 + d]
#pragma unroll
        for (int d = 0; d < 3; d++) {
            sScr[warp * 192 + r2 * 3 + d]       = pf[0][d];
            sScr[warp * 192 + (r2 + 1) * 3 + d] = pf[1][d];
        }
    }
    __syncthreads();

    // ---- finalize f = (sum over 8 warps) + b_out, * oscale ----
    if (t < TILE * NDIM) {
        int r = t / 3, d = t - 3 * r;
        int grow = row0 + r;
        float s = __ldg(b_out + d);
#pragma unroll
        for (int w = 0; w < 8; w++) s += sScr[w * 192 + t];
        if (grow < BTOT) out[grow * NDIM + d] = s * oscale;
    }

    // ---- g2 = (g3 @ Wt2) * (1 - h2^2) -> sH2 ----
    mmf2g<NHID>(sX, g_Wt2, r2, j0, acc);
    epi_bwd(acc, sH2, sH2, r2, j0);
    __syncthreads();

    // ---- g1 = (g2 @ Wt1) * (1 - h1^2) -> sH1 ----
    mmf2g<NHID>(sH2, g_Wt1, r2, j0, acc);
    epi_bwd(acc, sH1, sH1, r2, j0);
    __syncthreads();

    // ---- gz partials: 256 threads, r = t&63, quarter q = t>>6 ----
    {
        int r = t & 63, q = t >> 6;
        const float* Wn = W_in + q * 32;    // row d: W_in[d*NHID + q*32 + jj]
        float p0 = 0.0f, p1 = 0.0f, p2 = 0.0f;
#pragma unroll 8
        for (int jj = 0; jj < 32; jj++) {
            int j = q * 32 + jj;
            float g = sH1[j * TILE + r];
            p0 = fmaf(g, __ldg(Wn + 0 * NHID + jj), p0);
            p1 = fmaf(g, __ldg(Wn + 1 * NHID + jj), p1);
            p2 = fmaf(g, __ldg(Wn + 2 * NHID + jj), p2);
        }
        sScr[q * 192 + r * 3 + 0] = p0;
        sScr[q * 192 + r * 3 + 1] = p1;
        sScr[q * 192 + r * 3 + 2] = p2;
    }
    __syncthreads();

    if (t < TILE) {
        int r = t, grow = row0 + r;
        if (grow < BTOT) {
            float gz0 = 0.0f, gz1 = 0.0f, gz2 = 0.0f;
#pragma unroll
            for (int q = 0; q < 4; q++) {
                gz0 += sScr[q * 192 + r * 3 + 0];
                gz1 += sScr[q * 192 + r * 3 + 1];
                gz2 += sScr[q * 192 + r * 3 + 2];
            }
            float e0 = __ldg(eps + grow * NDIM + 0);
            float e1 = __ldg(eps + grow * NDIM + 1);
            float e2 = __ldg(eps + grow * NDIM + 2);
            out[BTOT * NDIM + grow] = -(gz0 * e0 + gz1 * e1 + gz2 * e2);
        }
    }
}

extern "C" void kernel_launch(void* const* d_in, const int* in_sizes, int n_in,
                              void* d_out, int out_size) {
    const float* t_p     = (const float*)d_in[0];
    const float* z       = (const float*)d_in[1];
    const float* context = (const float*)d_in[3];
    const float* eps     = (const float*)d_in[4];
    const float* W_in    = (const float*)d_in[5];
    const float* b_in    = (const float*)d_in[6];
    const float* W_h1    = (const float*)d_in[7];
    const float* b_h1    = (const float*)d_in[8];
    const float* W_h2    = (const float*)d_in[9];
    const float* b_h2    = (const float*)d_in[10];
    const float* W_out   = (const float*)d_in[11];
    const float* b_out   = (const float*)d_in[12];
    const float* scale_p = (const float*)d_in[13];
    float* out = (float*)d_out;

    const int smem_bytes = SM_TOTF * (int)sizeof(float);   // 105,984 B -> 2 CTAs/SM
    cudaFuncSetAttribute(ode_kernel, cudaFuncAttributeMaxDynamicSharedMemorySize, smem_bytes);

    transpose_k<<<(NHID * NHID + 255) / 256, 256>>>(W_h1, W_h2);

    const int grid = (BTOT + TILE - 1) / TILE;   // 7813
    ode_kernel<<<grid, NT, smem_bytes>>>(t_p, z, context, eps,
                                         W_in, b_in, W_h1, b_h1, W_h2, b_h2,
                                         W_out, b_out, scale_p, out);
}

// round 9
// speedup vs baseline: 1.3939x; 1.3939x over previous
#include <cuda_runtime.h>
#include <cstdint>

#define BTOT   500000
#define NDIM   3
#define NCOND  64
#define NHID   128
#define NIN    68      // NDIM + NCOND + 1
#define TILE   64
#define NT     256

typedef unsigned long long ull;

// Transposed hidden-layer weights for backward pass.
__device__ float g_Wt1[NHID * NHID];
__device__ float g_Wt2[NHID * NHID];

__global__ void transpose_k(const float* __restrict__ W1, const float* __restrict__ W2) {
    int idx = blockIdx.x * blockDim.x + threadIdx.x;
    if (idx < NHID * NHID) {
        int r = idx >> 7, c = idx & 127;
        g_Wt1[c * NHID + r] = W1[idx];
        g_Wt2[c * NHID + r] = W2[idx];
    }
}

__device__ __forceinline__ float ftanh(float x) {
    float e = __expf(2.0f * x);
    return __fdividef(e - 1.0f, e + 1.0f);
}

__device__ __forceinline__ ull pk(float lo, float hi) {
    ull r; asm("mov.b64 %0, {%1,%2};" : "=l"(r) : "f"(lo), "f"(hi)); return r;
}
__device__ __forceinline__ void upk(ull v, float& lo, float& hi) {
    asm("mov.b64 {%0,%1}, %2;" : "=f"(lo), "=f"(hi) : "l"(v));
}
__device__ __forceinline__ void fma2(ull& d, ull a, ull b) {
    asm("fma.rn.f32x2 %0, %1, %2, %3;" : "=l"(d) : "l"(a), "l"(b), "l"(d));
}

// acc[u][cp]: rows (r2+u), col-pair (j0+2cp, j0+2cp+1).
// sA: [K][TILE] transposed activations; sW: [K][NHID] row-major, both SMEM.
// A load: conflict-free LDS.64. W loads: 4x broadcast LDS.128.
template<int K, bool ZERO>
__device__ __forceinline__ void mmf2s(const float* __restrict__ sAct,
                                      const float* __restrict__ sW,
                                      int r2, int j0, ull acc[2][8]) {
    if (ZERO) {
#pragma unroll
        for (int u = 0; u < 2; u++)
#pragma unroll
            for (int c = 0; c < 8; c++) acc[u][c] = 0ULL;
    }
#pragma unroll 4
    for (int k = 0; k < K; k++) {
        float2 a = *reinterpret_cast<const float2*>(sAct + k * TILE + r2);
        ull a0 = pk(a.x, a.x);
        ull a1 = pk(a.y, a.y);
        const ulonglong2* wp = reinterpret_cast<const ulonglong2*>(sW + k * NHID + j0);
        ulonglong2 q0 = wp[0], q1 = wp[1], q2 = wp[2], q3 = wp[3];
        ull w[8] = {q0.x, q0.y, q1.x, q1.y, q2.x, q2.y, q3.x, q3.y};
#pragma unroll
        for (int c = 0; c < 8; c++) { fma2(acc[0][c], a0, w[c]); fma2(acc[1][c], a1, w[c]); }
    }
}

__device__ __forceinline__ void epi_tanh(ull acc[2][8], const float* __restrict__ bias,
                                         float* __restrict__ sH, int r2, int j0) {
#pragma unroll
    for (int c = 0; c < 8; c++) {
        int j = j0 + 2 * c;
        float b0 = __ldg(bias + j), b1 = __ldg(bias + j + 1);
        float x00, x01, x10, x11;
        upk(acc[0][c], x00, x01);
        upk(acc[1][c], x10, x11);
        *reinterpret_cast<float2*>(sH + j * TILE + r2) =
            make_float2(ftanh(x00 + b0), ftanh(x10 + b0));
        *reinterpret_cast<float2*>(sH + (j + 1) * TILE + r2) =
            make_float2(ftanh(x01 + b1), ftanh(x11 + b1));
    }
}

// dst = acc * (1 - h^2); per-thread-owned slots, dst may alias sHprev.
__device__ __forceinline__ void epi_bwd(ull acc[2][8], const float* __restrict__ sHprev,
                                        float* __restrict__ sDst, int r2, int j0) {
#pragma unroll
    for (int c = 0; c < 8; c++) {
        int j = j0 + 2 * c;
        float x00, x01, x10, x11;
        upk(acc[0][c], x00, x01);
        upk(acc[1][c], x10, x11);
        float2 h0 = *reinterpret_cast<const float2*>(sHprev + j * TILE + r2);
        float2 h1 = *reinterpret_cast<const float2*>(sHprev + (j + 1) * TILE + r2);
        *reinterpret_cast<float2*>(sDst + j * TILE + r2) =
            make_float2(x00 * (1.0f - h0.x * h0.x), x10 * (1.0f - h0.y * h0.y));
        *reinterpret_cast<float2*>(sDst + (j + 1) * TILE + r2) =
            make_float2(x01 * (1.0f - h1.x * h1.x), x11 * (1.0f - h1.y * h1.y));
    }
}

__device__ __forceinline__ void stage_cp(float* smDst, const float* g, int n4, int t) {
    unsigned int s = (unsigned int)__cvta_generic_to_shared(smDst);
    for (int i = t; i < n4; i += NT)
        asm volatile("cp.async.cg.shared.global [%0], [%1], 16;"
                     :: "r"(s + i * 16), "l"(g + i * 4));
}
#define CPA_COMMIT()  asm volatile("cp.async.commit_group;")
#define CPA_WAIT(n)   asm volatile("cp.async.wait_group %0;" :: "n"(n))

// SMEM layout (floats):
//   sA   [16384] : W_in(0:8704)+sIn(8704:13056) -> W_h2 -> {Wt1_lo(0:8192) | g3(8192:16384)} -> Wt1_hi(8192:16384)
//   sB   [16384] : W_h1 -> Wt2
//   sH1  [8192]  : h1 -> g1
//   sH2  [8192]  : h2 -> g2
//   sWout[384]
//   sScr [768]   : f partials (2 rounds), then gz partials (quarter scheme)
#define OFF_A     0
#define OFF_B     16384
#define OFF_H1    32768
#define OFF_H2    40960
#define OFF_WOUT  49152
#define OFF_SCR   49536
#define SM_TOTF   50304   // 201,216 bytes

__global__ __launch_bounds__(NT, 1)
void ode_kernel(const float* __restrict__ t_p,
                const float* __restrict__ z,
                const float* __restrict__ context,
                const float* __restrict__ eps,
                const float* __restrict__ W_in,  const float* __restrict__ b_in,
                const float* __restrict__ W_h1,  const float* __restrict__ b_h1,
                const float* __restrict__ W_h2,  const float* __restrict__ b_h2,
                const float* __restrict__ W_out, const float* __restrict__ b_out,
                const float* __restrict__ scale_p,
                float* __restrict__ out)
{
    extern __shared__ float sm[];
    float* sA    = sm + OFF_A;
    float* sB    = sm + OFF_B;
    float* sH1   = sm + OFF_H1;
    float* sH2   = sm + OFF_H2;
    float* sWout = sm + OFF_WOUT;
    float* sScr  = sm + OFF_SCR;
    float* sIn   = sA + 8704;          // 68*64 = 4352 floats
    float* sG3   = sA + 8192;          // g3 lives in upper half of A

    const int t    = threadIdx.x;
    const int lane = t & 31;
    const int warp = t >> 5;
    const int j0   = warp * 16;
    const int r2   = lane * 2;
    const int row0 = blockIdx.x * TILE;
    const float tval   = *t_p;
    const float oscale = *scale_p;

    // G0: W_in -> sA[0:8704] ; G1: W_h1 -> sB
    stage_cp(sA, W_in, (NIN * NHID) / 4, t); CPA_COMMIT();
    stage_cp(sB, W_h1, (NHID * NHID) / 4, t); CPA_COMMIT();

    // Input tile transposed sIn[k][r]; W_out copy; eps -> regs.
    for (int idx = t; idx < NIN * TILE; idx += NT) {
        int k = idx >> 6, r = idx & 63;
        int grow = row0 + r;
        float v = 0.0f;
        if (grow < BTOT) {
            if (k < NDIM)              v = z[grow * NDIM + k];
            else if (k < NDIM + NCOND) v = context[grow * NCOND + (k - NDIM)];
            else                       v = tval;
        }
        sIn[idx] = v;
    }
    for (int idx = t; idx < NHID * NDIM; idx += NT)
        sWout[idx] = __ldg(W_out + idx);

    float ep[2][3];
    {
        int ga = row0 + r2, gb = row0 + r2 + 1;
#pragma unroll
        for (int d = 0; d < 3; d++) {
            ep[0][d] = (ga < BTOT) ? __ldg(eps + ga * NDIM + d) : 0.0f;
            ep[1][d] = (gb < BTOT) ? __ldg(eps + gb * NDIM + d) : 0.0f;
        }
    }
    CPA_WAIT(1); __syncthreads();       // G0 done (W_h1 in flight)

    ull acc[2][8];

    // ---- L1: h1 = tanh(inp @ W_in + b_in) ----
    mmf2s<NIN, true>(sIn, sA, r2, j0, acc);
    epi_tanh(acc, b_in, sH1, r2, j0);
    __syncthreads();                    // everyone done with sA (W_in+sIn)

    stage_cp(sA, W_h2, (NHID * NHID) / 4, t); CPA_COMMIT();   // G2
    CPA_WAIT(1); __syncthreads();       // W_h1 ready

    // ---- L2 ----
    mmf2s<NHID, true>(sH1, sB, r2, j0, acc);
    epi_tanh(acc, b_h1, sH2, r2, j0);
    __syncthreads();                    // everyone done with sB (W_h1)

    stage_cp(sB, g_Wt2, (NHID * NHID) / 4, t); CPA_COMMIT();  // G3
    CPA_WAIT(1); __syncthreads();       // W_h2 ready

    // ---- L3: mm, then fused epilogue (h3 never leaves registers) ----
    mmf2s<NHID, true>(sH2, sA, r2, j0, acc);
    float h[2][16];
#pragma unroll
    for (int c = 0; c < 8; c++) {
        int j = j0 + 2 * c;
        float b0 = __ldg(b_h2 + j), b1 = __ldg(b_h2 + j + 1);
        float x00, x01, x10, x11;
        upk(acc[0][c], x00, x01);
        upk(acc[1][c], x10, x11);
        h[0][2*c]   = ftanh(x00 + b0);
        h[0][2*c+1] = ftanh(x01 + b1);
        h[1][2*c]   = ftanh(x10 + b0);
        h[1][2*c+1] = ftanh(x11 + b1);
    }
    __syncthreads();                    // all mm reads of sA (W_h2) complete

    // g3 -> sG3 (upper half of A); f partials -> regs
    {
        float pf[2][3] = {{0,0,0},{0,0,0}};
#pragma unroll
        for (int c = 0; c < 16; c++) {
            int j = j0 + c;
            float w0 = sWout[j * 3 + 0];
            float w1 = sWout[j * 3 + 1];
            float w2 = sWout[j * 3 + 2];
            float g3a = 0.0f, g3b = 0.0f;
#pragma unroll
            for (int u = 0; u < 2; u++) {
                float hv = h[u][c];
                pf[u][0] = fmaf(hv, w0, pf[u][0]);
                pf[u][1] = fmaf(hv, w1, pf[u][1]);
                pf[u][2] = fmaf(hv, w2, pf[u][2]);
                float s = ep[u][0] * w0 + ep[u][1] * w1 + ep[u][2] * w2;
                float g = s * oscale * (1.0f - hv * hv);
                if (u == 0) g3a = g; else g3b = g;
            }
            *reinterpret_cast<float2*>(sG3 + j * TILE + r2) = make_float2(g3a, g3b);
        }
        // Deterministic f reduction: round A (warps 0-3 write), round B (warps 4-7 add).
        if (warp < 4) {
#pragma unroll
            for (int d = 0; d < 3; d++) {
                sScr[warp * 192 + r2 * 3 + d]       = pf[0][d];
                sScr[warp * 192 + (r2 + 1) * 3 + d] = pf[1][d];
            }
        }
        __syncthreads();
        if (warp >= 4) {
            int w = warp - 4;
#pragma unroll
            for (int d = 0; d < 3; d++) {
                sScr[w * 192 + r2 * 3 + d]       += pf[0][d];
                sScr[w * 192 + (r2 + 1) * 3 + d] += pf[1][d];
            }
        }
    }
    __syncthreads();                    // g3 + f partials visible

    stage_cp(sA, g_Wt1, 8192 / 4, t); CPA_COMMIT();           // G4a: Wt1 rows 0..63 -> sA[0:8192]

    // ---- finalize f ----
    if (t < TILE * NDIM) {
        int r = t / 3, d = t - 3 * r;
        int grow = row0 + r;
        float s = __ldg(b_out + d) + sScr[t] + sScr[192 + t] + sScr[384 + t] + sScr[576 + t];
        if (grow < BTOT) out[grow * NDIM + d] = s * oscale;
    }

    CPA_WAIT(1); __syncthreads();       // Wt2 ready (G4a may still fly)

    // ---- g2 = (g3 @ Wt2) * (1 - h2^2) -> sH2 ----
    mmf2s<NHID, true>(sG3, sB, r2, j0, acc);
    epi_bwd(acc, sH2, sH2, r2, j0);
    __syncthreads();                    // all reads of sG3 done

    stage_cp(sG3, g_Wt1 + 8192, 8192 / 4, t); CPA_COMMIT();   // G4b: Wt1 rows 64..127 -> sA[8192:]

    CPA_WAIT(1); __syncthreads();       // G4a (Wt1 lo) ready

    // ---- g1 = (g2 @ Wt1) * (1 - h1^2), split around Wt1_hi arrival ----
    mmf2s<64, true>(sH2, sA, r2, j0, acc);                     // k in [0,64)
    CPA_WAIT(0); __syncthreads();       // Wt1 hi ready
    mmf2s<64, false>(sH2 + 64 * TILE, sA + 8192, r2, j0, acc); // k in [64,128)
    epi_bwd(acc, sH1, sH1, r2, j0);
    __syncthreads();

    // ---- gz partials: unique-slot quarter scheme into sScr ----
    {
        int r = t & 63, q = t >> 6;
        const float* Wn = W_in + q * 32;
        float p0 = 0.0f, p1 = 0.0f, p2 = 0.0f;
#pragma unroll 8
        for (int jj = 0; jj < 32; jj++) {
            int j = q * 32 + jj;
            float g = sH1[j * TILE + r];
            p0 = fmaf(g, __ldg(Wn + 0 * NHID + jj), p0);
            p1 = fmaf(g, __ldg(Wn + 1 * NHID + jj), p1);
            p2 = fmaf(g, __ldg(Wn + 2 * NHID + jj), p2);
        }
        sScr[q * 192 + r * 3 + 0] = p0;
        sScr[q * 192 + r * 3 + 1] = p1;
        sScr[q * 192 + r * 3 + 2] = p2;
    }
    __syncthreads();

    if (t < TILE) {
        int r = t, grow = row0 + r;
        if (grow < BTOT) {
            float gz0 = 0.0f, gz1 = 0.0f, gz2 = 0.0f;
#pragma unroll
            for (int q = 0; q < 4; q++) {
                gz0 += sScr[q * 192 + r * 3 + 0];
                gz1 += sScr[q * 192 + r * 3 + 1];
                gz2 += sScr[q * 192 + r * 3 + 2];
            }
            float e0 = __ldg(eps + grow * NDIM + 0);
            float e1 = __ldg(eps + grow * NDIM + 1);
            float e2 = __ldg(eps + grow * NDIM + 2);
            out[BTOT * NDIM + grow] = -(gz0 * e0 + gz1 * e1 + gz2 * e2);
        }
    }
}

extern "C" void kernel_launch(void* const* d_in, const int* in_sizes, int n_in,
                              void* d_out, int out_size) {
    const float* t_p     = (const float*)d_in[0];
    const float* z       = (const float*)d_in[1];
    const float* context = (const float*)d_in[3];
    const float* eps     = (const float*)d_in[4];
    const float* W_in    = (const float*)d_in[5];
    const float* b_in    = (const float*)d_in[6];
    const float* W_h1    = (const float*)d_in[7];
    const float* b_h1    = (const float*)d_in[8];
    const float* W_h2    = (const float*)d_in[9];
    const float* b_h2    = (const float*)d_in[10];
    const float* W_out   = (const float*)d_in[11];
    const float* b_out   = (const float*)d_in[12];
    const float* scale_p = (const float*)d_in[13];
    float* out = (float*)d_out;

    const int smem_bytes = SM_TOTF * (int)sizeof(float);   // 201,216 B
    cudaFuncSetAttribute(ode_kernel, cudaFuncAttributeMaxDynamicSharedMemorySize, smem_bytes);

    transpose_k<<<(NHID * NHID + 255) / 256, 256>>>(W_h1, W_h2);

    const int grid = (BTOT + TILE - 1) / TILE;   // 7813
    ode_kernel<<<grid, NT, smem_bytes>>>(t_p, z, context, eps,
                                         W_in, b_in, W_h1, b_h1, W_h2, b_h2,
                                         W_out, b_out, scale_p, out);
}

// round 11
// speedup vs baseline: 1.5672x; 1.1244x over previous
#include <cuda_runtime.h>
#include <cstdint>

#define BTOT   500000
#define NDIM   3
#define NCOND  64
#define NHID   128
#define NIN    68      // NDIM + NCOND + 1
#define TILE   64
#define NT     256

typedef unsigned long long ull;

// Transposed hidden-layer weights for backward pass.
__device__ float g_Wt1[NHID * NHID];
__device__ float g_Wt2[NHID * NHID];

__global__ void transpose_k(const float* __restrict__ W1, const float* __restrict__ W2) {
    int idx = blockIdx.x * blockDim.x + threadIdx.x;
    if (idx < NHID * NHID) {
        int r = idx >> 7, c = idx & 127;
        g_Wt1[c * NHID + r] = W1[idx];
        g_Wt2[c * NHID + r] = W2[idx];
    }
}

__device__ __forceinline__ float ftanh(float x) {
    float e = __expf(2.0f * x);
    return __fdividef(e - 1.0f, e + 1.0f);
}

__device__ __forceinline__ ull pk(float lo, float hi) {
    ull r; asm("mov.b64 %0, {%1,%2};" : "=l"(r) : "f"(lo), "f"(hi)); return r;
}
__device__ __forceinline__ void upk(ull v, float& lo, float& hi) {
    asm("mov.b64 {%0,%1}, %2;" : "=f"(lo), "=f"(hi) : "l"(v));
}
__device__ __forceinline__ void fma2(ull& d, ull a, ull b) {
    asm("fma.rn.f32x2 %0, %1, %2, %3;" : "=l"(d) : "l"(a), "l"(b), "l"(d));
}

// acc[u][c]: row (r4+u), col-pair (j0+2c, j0+2c+1). 16 FFMA2 per k.
// A: 1x LDS.128 (4 rows). W: 2x LDS.128, 2-way broadcast within warp.
template<int K, bool ZERO>
__device__ __forceinline__ void mmf4(const float* __restrict__ sAct,
                                     const float* __restrict__ sW,
                                     int r4, int j0, ull acc[4][4]) {
    if (ZERO) {
#pragma unroll
        for (int u = 0; u < 4; u++)
#pragma unroll
            for (int c = 0; c < 4; c++) acc[u][c] = 0ULL;
    }
#pragma unroll 4
    for (int k = 0; k < K; k++) {
        float4 a = *reinterpret_cast<const float4*>(sAct + k * TILE + r4);
        ull av[4] = {pk(a.x, a.x), pk(a.y, a.y), pk(a.z, a.z), pk(a.w, a.w)};
        ulonglong2 q0 = *reinterpret_cast<const ulonglong2*>(sW + k * NHID + j0);
        ulonglong2 q1 = *reinterpret_cast<const ulonglong2*>(sW + k * NHID + j0 + 4);
        ull w[4] = {q0.x, q0.y, q1.x, q1.y};
#pragma unroll
        for (int u = 0; u < 4; u++)
#pragma unroll
            for (int c = 0; c < 4; c++) fma2(acc[u][c], av[u], w[c]);
    }
}

__device__ __forceinline__ void epi_tanh4(ull acc[4][4], const float* __restrict__ bias,
                                          float* __restrict__ sH, int r4, int j0) {
#pragma unroll
    for (int c = 0; c < 4; c++) {
        int j = j0 + 2 * c;
        float b0 = __ldg(bias + j), b1 = __ldg(bias + j + 1);
        float xl[4], xh[4];
#pragma unroll
        for (int u = 0; u < 4; u++) upk(acc[u][c], xl[u], xh[u]);
        float4 v0 = make_float4(ftanh(xl[0] + b0), ftanh(xl[1] + b0),
                                ftanh(xl[2] + b0), ftanh(xl[3] + b0));
        float4 v1 = make_float4(ftanh(xh[0] + b1), ftanh(xh[1] + b1),
                                ftanh(xh[2] + b1), ftanh(xh[3] + b1));
        *reinterpret_cast<float4*>(sH + j * TILE + r4)       = v0;
        *reinterpret_cast<float4*>(sH + (j + 1) * TILE + r4) = v1;
    }
}

// dst = acc * (1 - h^2); per-thread-owned slots, dst may alias sHprev.
__device__ __forceinline__ void epi_bwd4(ull acc[4][4], const float* __restrict__ sHprev,
                                         float* __restrict__ sDst, int r4, int j0) {
#pragma unroll
    for (int c = 0; c < 4; c++) {
        int j = j0 + 2 * c;
        float4 h0 = *reinterpret_cast<const float4*>(sHprev + j * TILE + r4);
        float4 h1 = *reinterpret_cast<const float4*>(sHprev + (j + 1) * TILE + r4);
        float xl[4], xh[4];
#pragma unroll
        for (int u = 0; u < 4; u++) upk(acc[u][c], xl[u], xh[u]);
        float4 v0 = make_float4(xl[0] * (1.0f - h0.x * h0.x), xl[1] * (1.0f - h0.y * h0.y),
                                xl[2] * (1.0f - h0.z * h0.z), xl[3] * (1.0f - h0.w * h0.w));
        float4 v1 = make_float4(xh[0] * (1.0f - h1.x * h1.x), xh[1] * (1.0f - h1.y * h1.y),
                                xh[2] * (1.0f - h1.z * h1.z), xh[3] * (1.0f - h1.w * h1.w));
        *reinterpret_cast<float4*>(sDst + j * TILE + r4)       = v0;
        *reinterpret_cast<float4*>(sDst + (j + 1) * TILE + r4) = v1;
    }
}

__device__ __forceinline__ void stage_cp(float* smDst, const float* g, int n4, int t) {
    unsigned int s = (unsigned int)__cvta_generic_to_shared(smDst);
    for (int i = t; i < n4; i += NT)
        asm volatile("cp.async.cg.shared.global [%0], [%1], 16;"
                     :: "r"(s + i * 16), "l"(g + i * 4));
}
#define CPA_COMMIT()  asm volatile("cp.async.commit_group;")
#define CPA_WAIT(n)   asm volatile("cp.async.wait_group %0;" :: "n"(n))

// SMEM layout (floats):
//   sA   [16384] : W_in+sIn -> W_h2 -> {Wt1_lo | g3} -> Wt1_hi
//   sB   [16384] : W_h1 -> Wt2
//   sH1  [8192]  : h1
//   sH2  [8192]  : h2 -> g2
//   sWout[384], sWin3[384], sEps[192], sScr[1536]
#define OFF_A     0
#define OFF_B     16384
#define OFF_H1    32768
#define OFF_H2    40960
#define OFF_WOUT  49152
#define OFF_WIN3  49536
#define OFF_EPS   49920
#define OFF_SCR   50112
#define SM_TOTF   51648   // 206,592 bytes

__global__ __launch_bounds__(NT, 1)
void ode_kernel(const float* __restrict__ t_p,
                const float* __restrict__ z,
                const float* __restrict__ context,
                const float* __restrict__ eps,
                const float* __restrict__ W_in,  const float* __restrict__ b_in,
                const float* __restrict__ W_h1,  const float* __restrict__ b_h1,
                const float* __restrict__ W_h2,  const float* __restrict__ b_h2,
                const float* __restrict__ W_out, const float* __restrict__ b_out,
                const float* __restrict__ scale_p,
                float* __restrict__ out)
{
    extern __shared__ float sm[];
    float* sA    = sm + OFF_A;
    float* sB    = sm + OFF_B;
    float* sH1   = sm + OFF_H1;
    float* sH2   = sm + OFF_H2;
    float* sWout = sm + OFF_WOUT;
    float* sWin3 = sm + OFF_WIN3;
    float* sEps  = sm + OFF_EPS;
    float* sScr  = sm + OFF_SCR;
    float* sIn   = sA + 8704;          // 68*64 = 4352 floats
    float* sG3   = sA + 8192;          // g3 in upper half of A

    const int t    = threadIdx.x;
    const int rg   = t & 15;
    const int cg   = t >> 4;
    const int r4   = rg * 4;
    const int j0   = cg * 8;
    const int row0 = blockIdx.x * TILE;
    const float tval   = *t_p;
    const float oscale = *scale_p;

    // G0: W_in -> sA[0:8704] ; G1: W_h1 -> sB
    stage_cp(sA, W_in, (NIN * NHID) / 4, t); CPA_COMMIT();
    stage_cp(sB, W_h1, (NHID * NHID) / 4, t); CPA_COMMIT();

    // Input tile transposed sIn[k][r]; W_out copy; W_in rows 0..2; eps tile + regs.
    for (int idx = t; idx < NIN * TILE; idx += NT) {
        int k = idx >> 6, r = idx & 63;
        int grow = row0 + r;
        float v = 0.0f;
        if (grow < BTOT) {
            if (k < NDIM)              v = z[grow * NDIM + k];
            else if (k < NDIM + NCOND) v = context[grow * NCOND + (k - NDIM)];
            else                       v = tval;
        }
        sIn[idx] = v;
    }
    for (int idx = t; idx < NHID * NDIM; idx += NT) {
        sWout[idx] = __ldg(W_out + idx);
        sWin3[idx] = __ldg(W_in + idx);     // W_in[d][j] for d<3 = first 384 floats
    }
    if (t < TILE * NDIM) {
        int gi = row0 * NDIM + t;
        sEps[t] = (gi < BTOT * NDIM) ? __ldg(eps + gi) : 0.0f;
    }
    float ep[4][3];
#pragma unroll
    for (int u = 0; u < 4; u++) {
        int g = row0 + r4 + u;
#pragma unroll
        for (int d = 0; d < 3; d++)
            ep[u][d] = (g < BTOT) ? __ldg(eps + g * NDIM + d) : 0.0f;
    }
    CPA_WAIT(1); __syncthreads();       // G0 done (W_h1 in flight)

    ull acc[4][4];

    // ---- L1: h1 = tanh(inp @ W_in + b_in) ----
    mmf4<NIN, true>(sIn, sA, r4, j0, acc);
    epi_tanh4(acc, b_in, sH1, r4, j0);
    __syncthreads();                    // done with sA (W_in+sIn)

    stage_cp(sA, W_h2, (NHID * NHID) / 4, t); CPA_COMMIT();   // G2
    CPA_WAIT(1); __syncthreads();       // W_h1 ready

    // ---- L2 ----
    mmf4<NHID, true>(sH1, sB, r4, j0, acc);
    epi_tanh4(acc, b_h1, sH2, r4, j0);
    __syncthreads();                    // done with sB (W_h1)

    stage_cp(sB, g_Wt2, (NHID * NHID) / 4, t); CPA_COMMIT();  // G3
    CPA_WAIT(1); __syncthreads();       // W_h2 ready

    // ---- L3: mm, h3 stays in registers ----
    mmf4<NHID, true>(sH2, sA, r4, j0, acc);
    float h[4][8];
#pragma unroll
    for (int c = 0; c < 4; c++) {
        int j = j0 + 2 * c;
        float b0 = __ldg(b_h2 + j), b1 = __ldg(b_h2 + j + 1);
#pragma unroll
        for (int u = 0; u < 4; u++) {
            float xl, xh;
            upk(acc[u][c], xl, xh);
            h[u][2*c]   = ftanh(xl + b0);
            h[u][2*c+1] = ftanh(xh + b1);
        }
    }
    __syncthreads();                    // all mm reads of sA (W_h2) complete

    // g3 -> sG3; f partials -> regs
    {
        float pf[4][3] = {{0,0,0},{0,0,0},{0,0,0},{0,0,0}};
#pragma unroll
        for (int cc = 0; cc < 8; cc++) {
            int j = j0 + cc;
            float w0 = sWout[j * 3 + 0];
            float w1 = sWout[j * 3 + 1];
            float w2 = sWout[j * 3 + 2];
            float4 g3v;
            float* g3p = &g3v.x;
#pragma unroll
            for (int u = 0; u < 4; u++) {
                float hv = h[u][cc];
                pf[u][0] = fmaf(hv, w0, pf[u][0]);
                pf[u][1] = fmaf(hv, w1, pf[u][1]);
                pf[u][2] = fmaf(hv, w2, pf[u][2]);
                float s = ep[u][0] * w0 + ep[u][1] * w1 + ep[u][2] * w2;
                g3p[u] = s * oscale * (1.0f - hv * hv);
            }
            *reinterpret_cast<float4*>(sG3 + j * TILE + r4) = g3v;
        }
        // Deterministic f reduction: colgroups 0-7 write, 8-15 add.
        if (cg < 8) {
#pragma unroll
            for (int u = 0; u < 4; u++)
#pragma unroll
                for (int d = 0; d < 3; d++)
                    sScr[cg * 192 + (r4 + u) * 3 + d] = pf[u][d];
        }
        __syncthreads();
        if (cg >= 8) {
#pragma unroll
            for (int u = 0; u < 4; u++)
#pragma unroll
                for (int d = 0; d < 3; d++)
                    sScr[(cg - 8) * 192 + (r4 + u) * 3 + d] += pf[u][d];
        }
    }
    __syncthreads();                    // g3 + f partials visible

    stage_cp(sA, g_Wt1, 8192 / 4, t); CPA_COMMIT();           // G4a: Wt1 rows 0..63

    // ---- finalize f ----
    if (t < TILE * NDIM) {
        int r = t / 3, d = t - 3 * r;
        int grow = row0 + r;
        float s = __ldg(b_out + d);
#pragma unroll
        for (int g = 0; g < 8; g++) s += sScr[g * 192 + t];
        if (grow < BTOT) out[grow * NDIM + d] = s * oscale;
    }

    CPA_WAIT(1); __syncthreads();       // Wt2 ready

    // ---- g2 = (g3 @ Wt2) * (1 - h2^2) -> sH2 ----
    mmf4<NHID, true>(sG3, sB, r4, j0, acc);
    epi_bwd4(acc, sH2, sH2, r4, j0);
    __syncthreads();                    // all reads of sG3 done

    stage_cp(sG3, g_Wt1 + 8192, 8192 / 4, t); CPA_COMMIT();   // G4b: Wt1 rows 64..127
    CPA_WAIT(1); __syncthreads();       // G4a (Wt1 lo) ready

    // ---- g1 = (g2 @ Wt1) * (1 - h1^2), fused with gz partials ----
    mmf4<64, true>(sH2, sA, r4, j0, acc);                      // k in [0,64)
    CPA_WAIT(0); __syncthreads();       // Wt1 hi ready
    mmf4<64, false>(sH2 + 64 * TILE, sA + 8192, r4, j0, acc);  // k in [64,128)
    {
        float gzp[4][3] = {{0,0,0},{0,0,0},{0,0,0},{0,0,0}};
#pragma unroll
        for (int c = 0; c < 4; c++) {
            int j = j0 + 2 * c;
            float4 h0 = *reinterpret_cast<const float4*>(sH1 + j * TILE + r4);
            float4 h1 = *reinterpret_cast<const float4*>(sH1 + (j + 1) * TILE + r4);
            const float* h0p = &h0.x;
            const float* h1p = &h1.x;
#pragma unroll
            for (int u = 0; u < 4; u++) {
                float xl, xh;
                upk(acc[u][c], xl, xh);
                float glo = xl * (1.0f - h0p[u] * h0p[u]);
                float ghi = xh * (1.0f - h1p[u] * h1p[u]);
#pragma unroll
                for (int d = 0; d < 3; d++)
                    gzp[u][d] += glo * sWin3[d * NHID + j] + ghi * sWin3[d * NHID + j + 1];
            }
        }
        __syncthreads();                // f-reduction reads of sScr done everywhere
        if (cg < 8) {
#pragma unroll
            for (int u = 0; u < 4; u++)
#pragma unroll
                for (int d = 0; d < 3; d++)
                    sScr[cg * 192 + (r4 + u) * 3 + d] = gzp[u][d];
        }
        __syncthreads();
        if (cg >= 8) {
#pragma unroll
            for (int u = 0; u < 4; u++)
#pragma unroll
                for (int d = 0; d < 3; d++)
                    sScr[(cg - 8) * 192 + (r4 + u) * 3 + d] += gzp[u][d];
        }
    }
    __syncthreads();

    // ---- neg_div = -(gz . eps) ----
    if (t < TILE) {
        int r = t, grow = row0 + r;
        if (grow < BTOT) {
            float nd = 0.0f;
#pragma unroll
            for (int d = 0; d < 3; d++) {
                float gz = 0.0f;
#pragma unroll
                for (int g = 0; g < 8; g++) gz += sScr[g * 192 + r * 3 + d];
                nd = fmaf(gz, sEps[r * 3 + d], nd);
            }
            out[BTOT * NDIM + grow] = -nd;
        }
    }
}

extern "C" void kernel_launch(void* const* d_in, const int* in_sizes, int n_in,
                              void* d_out, int out_size) {
    const float* t_p     = (const float*)d_in[0];
    const float* z       = (const float*)d_in[1];
    const float* context = (const float*)d_in[3];
    const float* eps     = (const float*)d_in[4];
    const float* W_in    = (const float*)d_in[5];
    const float* b_in    = (const float*)d_in[6];
    const float* W_h1    = (const float*)d_in[7];
    const float* b_h1    = (const float*)d_in[8];
    const float* W_h2    = (const float*)d_in[9];
    const float* b_h2    = (const float*)d_in[10];
    const float* W_out   = (const float*)d_in[11];
    const float* b_out   = (const float*)d_in[12];
    const float* scale_p = (const float*)d_in[13];
    float* out = (float*)d_out;

    const int smem_bytes = SM_TOTF * (int)sizeof(float);   // 206,592 B
    cudaFuncSetAttribute(ode_kernel, cudaFuncAttributeMaxDynamicSharedMemorySize, smem_bytes);

    transpose_k<<<(NHID * NHID + 255) / 256, 256>>>(W_h1, W_h2);

    const int grid = (BTOT + TILE - 1) / TILE;   // 7813
    ode_kernel<<<grid, NT, smem_bytes>>>(t_p, z, context, eps,
                                         W_in, b_in, W_h1, b_h1, W_h2, b_h2,
                                         W_out, b_out, scale_p, out);
}

// round 13
// speedup vs baseline: 2.4705x; 1.5763x over previous
#include <cuda_runtime.h>
#include <cuda_bf16.h>
#include <cstdint>

#define BTOT   500000
#define NDIM   3
#define NCOND  64
#define NHID   128
#define NIN    68
#define TILE   128
#define NT     256

// SMEM byte offsets
#define X_HI   0
#define X_LO   32768
#define H1_HI  65536
#define H1_LO  98304
#define H2_HI  131072
#define H2_LO  163840
#define B_SL   196608          // 32KB weight staging slot
#define WOUT   229376          // 384 floats
#define SM_TOT 230912

// Pre-split, pre-swizzled weight operands: [which][hi/lo][32KB]
// which: 0=W_in^T(padK) 1=W_h1^T 2=W_h2^T 3=W_h2 4=W_h1
__device__ __align__(16) unsigned char g_B[5][2][32768];

// XOR-swizzled K-major layout: row stride 256B (128 bf16), 16B chunks,
// physical chunk = chunk ^ (row & 7)  -> conflict-free 8-row LDSM.
__device__ __forceinline__ int swoff(int r, int k) {
    return r * 256 + ((((k >> 3) ^ (r & 7)) & 15) << 4) + (k & 7) * 2;
}
__device__ __forceinline__ uint32_t swbase(int r, int kb) {   // kb multiple of 8
    return (uint32_t)(r * 256 + ((((kb >> 3) ^ (r & 7)) & 15) << 4));
}

__global__ void prep_k(const float* __restrict__ Wi, const float* __restrict__ W1,
                       const float* __restrict__ W2) {
    int idx = blockIdx.x * blockDim.x + threadIdx.x;
    if (idx >= 5 * NHID * NHID) return;
    int t = idx >> 14, e = idx & 16383, n = e >> 7, k = e & 127;
    float v;
    switch (t) {
        case 0:  v = (k < NIN) ? Wi[k * NHID + n] : 0.0f; break;  // fwd L1
        case 1:  v = W1[k * NHID + n]; break;                     // fwd L2
        case 2:  v = W2[k * NHID + n]; break;                     // fwd L3
        case 3:  v = W2[n * NHID + k]; break;                     // bwd g2
        default: v = W1[n * NHID + k]; break;                     // bwd g1
    }
    unsigned short hb = __bfloat16_as_ushort(__float2bfloat16(v));
    float rem = v - __uint_as_float((unsigned)hb << 16);
    unsigned short lb = __bfloat16_as_ushort(__float2bfloat16(rem));
    int o = swoff(n, k);
    *(unsigned short*)(g_B[t][0] + o) = hb;
    *(unsigned short*)(g_B[t][1] + o) = lb;
}

__device__ __forceinline__ float ftanh(float x) {
    float e = __expf(2.0f * x);
    return __fdividef(e - 1.0f, e + 1.0f);
}

__device__ __forceinline__ void ldsm4(uint32_t a[4], uint32_t addr) {
    asm volatile("ldmatrix.sync.aligned.m8n8.x4.shared.b16 {%0,%1,%2,%3}, [%4];"
        : "=r"(a[0]), "=r"(a[1]), "=r"(a[2]), "=r"(a[3]) : "r"(addr));
}
__device__ __forceinline__ void mma16816(float d[4], const uint32_t a[4],
                                         uint32_t b0, uint32_t b1) {
    asm volatile("mma.sync.aligned.m16n8k16.row.col.f32.bf16.bf16.f32 "
        "{%0,%1,%2,%3}, {%4,%5,%6,%7}, {%8,%9}, {%0,%1,%2,%3};"
        : "+f"(d[0]), "+f"(d[1]), "+f"(d[2]), "+f"(d[3])
        : "r"(a[0]), "r"(a[1]), "r"(a[2]), "r"(a[3]), "r"(b0), "r"(b1));
}

__device__ __forceinline__ void split_store(unsigned char* smb, int hiB, int loB,
                                            int r, int c, float v0, float v1) {
    unsigned ah = __bfloat16_as_ushort(__float2bfloat16(v0));
    unsigned bh = __bfloat16_as_ushort(__float2bfloat16(v1));
    float ar = v0 - __uint_as_float(ah << 16);
    float br = v1 - __uint_as_float(bh << 16);
    unsigned al = __bfloat16_as_ushort(__float2bfloat16(ar));
    unsigned bl = __bfloat16_as_ushort(__float2bfloat16(br));
    int o = swoff(r, c);
    *(uint32_t*)(smb + hiB + o) = ah | (bh << 16);
    *(uint32_t*)(smb + loB + o) = al | (bl << 16);
}
__device__ __forceinline__ void ld_pair(const unsigned char* smb, int hiB, int loB,
                                        int r, int c, float& v0, float& v1) {
    int o = swoff(r, c);
    uint32_t wh = *(const uint32_t*)(smb + hiB + o);
    uint32_t wl = *(const uint32_t*)(smb + loB + o);
    v0 = __uint_as_float(wh << 16)         + __uint_as_float(wl << 16);
    v1 = __uint_as_float(wh & 0xFFFF0000u) + __uint_as_float(wl & 0xFFFF0000u);
}

__device__ __forceinline__ void stageB(unsigned char* smb, const unsigned char* src) {
    uint32_t s = (uint32_t)__cvta_generic_to_shared(smb + B_SL);
    for (int i = threadIdx.x; i < 2048; i += NT)
        asm volatile("cp.async.cg.shared.global [%0], [%1], 16;"
                     :: "r"(s + i * 16), "l"(src + i * 16));
    asm volatile("cp.async.commit_group;");
    asm volatile("cp.async.wait_group 0;");
}

// One GEMM: acc = Ahi*Bhi + Alo*Bhi + Ahi*Blo   (K = KS*16)
template<int KS>
__device__ __forceinline__ void run_gemm(unsigned char* smb, uint32_t smu, int bIdx,
                                         int aHiOff, int aLoOff,
                                         int a_r, int a_kadd, int b_radd, int b_kadd,
                                         float acc[16][4]) {
#pragma unroll
    for (int p = 0; p < 16; p++)
#pragma unroll
        for (int q = 0; q < 4; q++) acc[p][q] = 0.0f;

    __syncthreads();                         // B_SL free, A buffers complete
    stageB(smb, g_B[bIdx][0]);
    __syncthreads();
    const uint32_t aHiU = smu + aHiOff, aLoU = smu + aLoOff, bU = smu + B_SL;
#pragma unroll
    for (int ks = 0; ks < KS; ks++) {
        uint32_t ahi[4], alo[4];
        ldsm4(ahi, aHiU + swbase(a_r, ks * 16 + a_kadd));
        ldsm4(alo, aLoU + swbase(a_r, ks * 16 + a_kadd));
#pragma unroll
        for (int p = 0; p < 8; p++) {
            uint32_t b[4];
            ldsm4(b, bU + swbase(p * 16 + b_radd, ks * 16 + b_kadd));
            mma16816(acc[2 * p],     ahi, b[0], b[1]);
            mma16816(acc[2 * p + 1], ahi, b[2], b[3]);
            mma16816(acc[2 * p],     alo, b[0], b[1]);
            mma16816(acc[2 * p + 1], alo, b[2], b[3]);
        }
    }
    __syncthreads();                         // done reading Bhi
    stageB(smb, g_B[bIdx][1]);
    __syncthreads();
#pragma unroll
    for (int ks = 0; ks < KS; ks++) {
        uint32_t ahi[4];
        ldsm4(ahi, aHiU + swbase(a_r, ks * 16 + a_kadd));
#pragma unroll
        for (int p = 0; p < 8; p++) {
            uint32_t b[4];
            ldsm4(b, bU + swbase(p * 16 + b_radd, ks * 16 + b_kadd));
            mma16816(acc[2 * p],     ahi, b[0], b[1]);
            mma16816(acc[2 * p + 1], ahi, b[2], b[3]);
        }
    }
}

__global__ __launch_bounds__(NT, 1)
void ode_mma(const float* __restrict__ t_p,
             const float* __restrict__ z,
             const float* __restrict__ context,
             const float* __restrict__ eps,
             const float* __restrict__ W_in, const float* __restrict__ b_in,
             const float* __restrict__ b_h1, const float* __restrict__ b_h2,
             const float* __restrict__ W_out, const float* __restrict__ b_out,
             const float* __restrict__ scale_p,
             float* __restrict__ out)
{
    extern __shared__ unsigned char smb[];
    uint32_t smu = (uint32_t)__cvta_generic_to_shared(smb);
    float* sWout = (float*)(smb + WOUT);

    const int t    = threadIdx.x;
    const int warp = t >> 5;
    const int lane = t & 31;
    const int row0 = blockIdx.x * TILE;
    const float tval   = *t_p;
    const float oscale = *scale_p;

    // ldmatrix lane address parameters
    const int sub = lane >> 3, ro = lane & 7;
    const int a_r    = warp * 16 + ((sub & 1) << 3) + ro;
    const int a_kadd = (sub >> 1) << 3;
    const int b_radd = ((sub >> 1) << 3) + ro;
    const int b_kadd = (sub & 1) << 3;

    // epilogue thread mapping
    const int g  = lane >> 2, qi = lane & 3;
    const int r0 = warp * 16 + g, r1 = r0 + 8;
    const int grow0 = row0 + r0, grow1 = row0 + r1;

    // ---- stage input tile (hi/lo bf16, K=80 zero-padded) + W_out + eps ----
    {
        int r = t >> 1, half = t & 1;
        int grow = row0 + r;
        bool valid = grow < BTOT;
        int kbeg = half * 64, kend = half ? 80 : 64;
        for (int k = kbeg; k < kend; k += 2) {
            float v0 = 0.0f, v1 = 0.0f;
            if (valid) {
                v0 = (k < NDIM) ? z[grow * NDIM + k]
                   : (k < NIN - 1) ? __ldg(context + grow * NCOND + (k - NDIM))
                   : (k == NIN - 1) ? tval : 0.0f;
                int k1 = k + 1;
                v1 = (k1 < NDIM) ? z[grow * NDIM + k1]
                   : (k1 < NIN - 1) ? __ldg(context + grow * NCOND + (k1 - NDIM))
                   : (k1 == NIN - 1) ? tval : 0.0f;
            }
            split_store(smb, X_HI, X_LO, r, k, v0, v1);
        }
    }
    for (int idx = t; idx < NHID * NDIM; idx += NT) sWout[idx] = __ldg(W_out + idx);

    float ep0[3], ep1[3];
#pragma unroll
    for (int d = 0; d < 3; d++) {
        ep0[d] = (grow0 < BTOT) ? __ldg(eps + grow0 * NDIM + d) : 0.0f;
        ep1[d] = (grow1 < BTOT) ? __ldg(eps + grow1 * NDIM + d) : 0.0f;
    }

    float acc[16][4];

    // ==== L1: h1 = tanh(in @ W_in + b_in) ====
    run_gemm<5>(smb, smu, 0, X_HI, X_LO, a_r, a_kadd, b_radd, b_kadd, acc);
#pragma unroll
    for (int p = 0; p < 16; p++) {
        int c = p * 8 + qi * 2;
        float b0 = __ldg(b_in + c), b1 = __ldg(b_in + c + 1);
        split_store(smb, H1_HI, H1_LO, r0, c, ftanh(acc[p][0] + b0), ftanh(acc[p][1] + b1));
        split_store(smb, H1_HI, H1_LO, r1, c, ftanh(acc[p][2] + b0), ftanh(acc[p][3] + b1));
    }

    // ==== L2: h2 = tanh(h1 @ W_h1 + b_h1) ====
    run_gemm<8>(smb, smu, 1, H1_HI, H1_LO, a_r, a_kadd, b_radd, b_kadd, acc);
#pragma unroll
    for (int p = 0; p < 16; p++) {
        int c = p * 8 + qi * 2;
        float b0 = __ldg(b_h1 + c), b1 = __ldg(b_h1 + c + 1);
        split_store(smb, H2_HI, H2_LO, r0, c, ftanh(acc[p][0] + b0), ftanh(acc[p][1] + b1));
        split_store(smb, H2_HI, H2_LO, r1, c, ftanh(acc[p][2] + b0), ftanh(acc[p][3] + b1));
    }

    // ==== L3: h3 in regs; f per-row; g3 -> X ====
    run_gemm<8>(smb, smu, 2, H2_HI, H2_LO, a_r, a_kadd, b_radd, b_kadd, acc);
    {
        float pf0[3] = {0, 0, 0}, pf1[3] = {0, 0, 0};
#pragma unroll
        for (int p = 0; p < 16; p++) {
            int c = p * 8 + qi * 2;
            float b0 = __ldg(b_h2 + c), b1 = __ldg(b_h2 + c + 1);
            float h00 = ftanh(acc[p][0] + b0), h01 = ftanh(acc[p][1] + b1);
            float h10 = ftanh(acc[p][2] + b0), h11 = ftanh(acc[p][3] + b1);
            float wa0 = sWout[c * 3 + 0], wa1 = sWout[c * 3 + 1], wa2 = sWout[c * 3 + 2];
            float wb0 = sWout[c * 3 + 3], wb1 = sWout[c * 3 + 4], wb2 = sWout[c * 3 + 5];
            pf0[0] += h00 * wa0 + h01 * wb0;
            pf0[1] += h00 * wa1 + h01 * wb1;
            pf0[2] += h00 * wa2 + h01 * wb2;
            pf1[0] += h10 * wa0 + h11 * wb0;
            pf1[1] += h10 * wa1 + h11 * wb1;
            pf1[2] += h10 * wa2 + h11 * wb2;
            float s0a = ep0[0] * wa0 + ep0[1] * wa1 + ep0[2] * wa2;
            float s0b = ep0[0] * wb0 + ep0[1] * wb1 + ep0[2] * wb2;
            float s1a = ep1[0] * wa0 + ep1[1] * wa1 + ep1[2] * wa2;
            float s1b = ep1[0] * wb0 + ep1[1] * wb1 + ep1[2] * wb2;
            split_store(smb, X_HI, X_LO, r0, c,
                        s0a * oscale * (1.0f - h00 * h00),
                        s0b * oscale * (1.0f - h01 * h01));
            split_store(smb, X_HI, X_LO, r1, c,
                        s1a * oscale * (1.0f - h10 * h10),
                        s1b * oscale * (1.0f - h11 * h11));
        }
#pragma unroll
        for (int d = 0; d < 3; d++) {
            pf0[d] += __shfl_down_sync(0xffffffffu, pf0[d], 2, 4);
            pf0[d] += __shfl_down_sync(0xffffffffu, pf0[d], 1, 4);
            pf1[d] += __shfl_down_sync(0xffffffffu, pf1[d], 2, 4);
            pf1[d] += __shfl_down_sync(0xffffffffu, pf1[d], 1, 4);
        }
        if (qi == 0) {
#pragma unroll
            for (int d = 0; d < 3; d++) {
                if (grow0 < BTOT) out[grow0 * NDIM + d] = (pf0[d] + __ldg(b_out + d)) * oscale;
                if (grow1 < BTOT) out[grow1 * NDIM + d] = (pf1[d] + __ldg(b_out + d)) * oscale;
            }
        }
    }

    // ==== g2 = (g3 @ W_h2) * (1 - h2^2) -> X (rows warp-private) ====
    run_gemm<8>(smb, smu, 3, X_HI, X_LO, a_r, a_kadd, b_radd, b_kadd, acc);
#pragma unroll
    for (int p = 0; p < 16; p++) {
        int c = p * 8 + qi * 2;
        float h00, h01, h10, h11;
        ld_pair(smb, H2_HI, H2_LO, r0, c, h00, h01);
        ld_pair(smb, H2_HI, H2_LO, r1, c, h10, h11);
        split_store(smb, X_HI, X_LO, r0, c,
                    acc[p][0] * (1.0f - h00 * h00), acc[p][1] * (1.0f - h01 * h01));
        split_store(smb, X_HI, X_LO, r1, c,
                    acc[p][2] * (1.0f - h10 * h10), acc[p][3] * (1.0f - h11 * h11));
    }

    // ==== g1 = (g2 @ W_h1) * (1 - h1^2); gz; neg_div ====
    run_gemm<8>(smb, smu, 4, X_HI, X_LO, a_r, a_kadd, b_radd, b_kadd, acc);
    {
        float gz0[3] = {0, 0, 0}, gz1[3] = {0, 0, 0};
#pragma unroll
        for (int p = 0; p < 16; p++) {
            int c = p * 8 + qi * 2;
            float h00, h01, h10, h11;
            ld_pair(smb, H1_HI, H1_LO, r0, c, h00, h01);
            ld_pair(smb, H1_HI, H1_LO, r1, c, h10, h11);
            float g00 = acc[p][0] * (1.0f - h00 * h00);
            float g01 = acc[p][1] * (1.0f - h01 * h01);
            float g10 = acc[p][2] * (1.0f - h10 * h10);
            float g11 = acc[p][3] * (1.0f - h11 * h11);
#pragma unroll
            for (int d = 0; d < 3; d++) {
                float w0 = __ldg(W_in + d * NHID + c);
                float w1 = __ldg(W_in + d * NHID + c + 1);
                gz0[d] += g00 * w0 + g01 * w1;
                gz1[d] += g10 * w0 + g11 * w1;
            }
        }
#pragma unroll
        for (int d = 0; d < 3; d++) {
            gz0[d] += __shfl_down_sync(0xffffffffu, gz0[d], 2, 4);
            gz0[d] += __shfl_down_sync(0xffffffffu, gz0[d], 1, 4);
            gz1[d] += __shfl_down_sync(0xffffffffu, gz1[d], 2, 4);
            gz1[d] += __shfl_down_sync(0xffffffffu, gz1[d], 1, 4);
        }
        if (qi == 0) {
            if (grow0 < BTOT)
                out[BTOT * NDIM + grow0] = -(gz0[0] * ep0[0] + gz0[1] * ep0[1] + gz0[2] * ep0[2]);
            if (grow1 < BTOT)
                out[BTOT * NDIM + grow1] = -(gz1[0] * ep1[0] + gz1[1] * ep1[1] + gz1[2] * ep1[2]);
        }
    }
}

extern "C" void kernel_launch(void* const* d_in, const int* in_sizes, int n_in,
                              void* d_out, int out_size) {
    const float* t_p     = (const float*)d_in[0];
    const float* z       = (const float*)d_in[1];
    const float* context = (const float*)d_in[3];
    const float* eps     = (const float*)d_in[4];
    const float* W_in    = (const float*)d_in[5];
    const float* b_in    = (const float*)d_in[6];
    const float* W_h1    = (const float*)d_in[7];
    const float* b_h1    = (const float*)d_in[8];
    const float* W_h2    = (const float*)d_in[9];
    const float* b_h2    = (const float*)d_in[10];
    const float* W_out   = (const float*)d_in[11];
    const float* b_out   = (const float*)d_in[12];
    const float* scale_p = (const float*)d_in[13];
    float* out = (float*)d_out;

    cudaFuncSetAttribute(ode_mma, cudaFuncAttributeMaxDynamicSharedMemorySize, SM_TOT);

    prep_k<<<(5 * NHID * NHID + 255) / 256, 256>>>(W_in, W_h1, W_h2);

    const int grid = (BTOT + TILE - 1) / TILE;   // 3907
    ode_mma<<<grid, NT, SM_TOT>>>(t_p, z, context, eps,
                                  W_in, b_in, b_h1, b_h2,
                                  W_out, b_out, scale_p, out);
}

// round 14
// speedup vs baseline: 3.4667x; 1.4033x over previous
#include <cuda_runtime.h>
#include <cuda_fp16.h>
#include <cstdint>

#define BTOT   500000
#define NDIM   3
#define NCOND  64
#define NHID   128
#define NIN    68
#define TILE   128
#define NT     256

// SMEM byte offsets
#define X_HI   0
#define X_LO   32768
#define H1_HI  65536
#define H1_LO  98304
#define H2_HI  131072
#define H2_LO  163840
#define B_SL   196608          // 32KB weight staging slot
#define WOUT   229376          // 384 floats
#define SM_TOT 230912

// Pre-swizzled fp16 weight operands: 0=W_in^T(padK) 1=W_h1^T 2=W_h2^T 3=W_h2 4=W_h1
__device__ __align__(16) unsigned char g_B[5][32768];

// XOR-swizzled K-major layout: row stride 256B (128 fp16), 16B chunks,
// physical chunk = chunk ^ (row & 7)  -> conflict-free 8-row LDSM.
__device__ __forceinline__ int swoff(int r, int k) {
    return r * 256 + ((((k >> 3) ^ (r & 7)) & 15) << 4) + (k & 7) * 2;
}
__device__ __forceinline__ uint32_t swbase(int r, int kb) {
    return (uint32_t)(r * 256 + ((((kb >> 3) ^ (r & 7)) & 15) << 4));
}

__global__ void prep_k(const float* __restrict__ Wi, const float* __restrict__ W1,
                       const float* __restrict__ W2) {
    int idx = blockIdx.x * blockDim.x + threadIdx.x;
    if (idx >= 5 * NHID * NHID) return;
    int t = idx >> 14, e = idx & 16383, n = e >> 7, k = e & 127;
    float v;
    switch (t) {
        case 0:  v = (k < NIN) ? Wi[k * NHID + n] : 0.0f; break;  // fwd L1
        case 1:  v = W1[k * NHID + n]; break;                     // fwd L2
        case 2:  v = W2[k * NHID + n]; break;                     // fwd L3
        case 3:  v = W2[n * NHID + k]; break;                     // bwd g2
        default: v = W1[n * NHID + k]; break;                     // bwd g1
    }
    *(unsigned short*)(g_B[t] + swoff(n, k)) = __half_as_ushort(__float2half_rn(v));
}

__device__ __forceinline__ float ftanh(float x) {
    float e = __expf(2.0f * x);
    return __fdividef(e - 1.0f, e + 1.0f);
}

__device__ __forceinline__ void ldsm4(uint32_t a[4], uint32_t addr) {
    asm volatile("ldmatrix.sync.aligned.m8n8.x4.shared.b16 {%0,%1,%2,%3}, [%4];"
        : "=r"(a[0]), "=r"(a[1]), "=r"(a[2]), "=r"(a[3]) : "r"(addr));
}
__device__ __forceinline__ void mma16816(float d[4], const uint32_t a[4],
                                         uint32_t b0, uint32_t b1) {
    asm volatile("mma.sync.aligned.m16n8k16.row.col.f32.f16.f16.f32 "
        "{%0,%1,%2,%3}, {%4,%5,%6,%7}, {%8,%9}, {%0,%1,%2,%3};"
        : "+f"(d[0]), "+f"(d[1]), "+f"(d[2]), "+f"(d[3])
        : "r"(a[0]), "r"(a[1]), "r"(a[2]), "r"(a[3]), "r"(b0), "r"(b1));
}

__device__ __forceinline__ void split_store(unsigned char* smb, int hiB, int loB,
                                            int r, int c, float v0, float v1) {
    __half h0 = __float2half_rn(v0), h1 = __float2half_rn(v1);
    __half l0 = __float2half_rn(v0 - __half2float(h0));
    __half l1 = __float2half_rn(v1 - __half2float(h1));
    int o = swoff(r, c);
    *(uint32_t*)(smb + hiB + o) =
        (uint32_t)__half_as_ushort(h0) | ((uint32_t)__half_as_ushort(h1) << 16);
    *(uint32_t*)(smb + loB + o) =
        (uint32_t)__half_as_ushort(l0) | ((uint32_t)__half_as_ushort(l1) << 16);
}
__device__ __forceinline__ void ld_pair(const unsigned char* smb, int hiB, int loB,
                                        int r, int c, float& v0, float& v1) {
    int o = swoff(r, c);
    uint32_t wh = *(const uint32_t*)(smb + hiB + o);
    uint32_t wl = *(const uint32_t*)(smb + loB + o);
    v0 = __half2float(__ushort_as_half((unsigned short)(wh & 0xFFFFu)))
       + __half2float(__ushort_as_half((unsigned short)(wl & 0xFFFFu)));
    v1 = __half2float(__ushort_as_half((unsigned short)(wh >> 16)))
       + __half2float(__ushort_as_half((unsigned short)(wl >> 16)));
}

__device__ __forceinline__ void stageB_async(unsigned char* smb, const unsigned char* src) {
    uint32_t s = (uint32_t)__cvta_generic_to_shared(smb + B_SL);
    for (int i = threadIdx.x; i < 2048; i += NT)
        asm volatile("cp.async.cg.shared.global [%0], [%1], 16;"
                     :: "r"(s + i * 16), "l"(src + i * 16));
    asm volatile("cp.async.commit_group;");
}
#define CPA_WAIT0() asm volatile("cp.async.wait_group 0;")

// Single-sweep GEMM: acc = Ahi*B + Alo*B (B fp16 exact, K = KS*16).
// On entry B is staged & synced. On exit: synced, next B prefetch may be issued.
template<int KS>
__device__ __forceinline__ void run_gemm(unsigned char* smb, uint32_t smu,
                                         int aHiOff, int aLoOff,
                                         int a_r, int a_kadd, int b_radd, int b_kadd,
                                         float acc[16][4]) {
#pragma unroll
    for (int p = 0; p < 16; p++)
#pragma unroll
        for (int q = 0; q < 4; q++) acc[p][q] = 0.0f;

    const uint32_t aHiU = smu + aHiOff, aLoU = smu + aLoOff, bU = smu + B_SL;
#pragma unroll
    for (int ks = 0; ks < KS; ks++) {
        uint32_t ahi[4], alo[4];
        ldsm4(ahi, aHiU + swbase(a_r, ks * 16 + a_kadd));
        ldsm4(alo, aLoU + swbase(a_r, ks * 16 + a_kadd));
#pragma unroll
        for (int p = 0; p < 8; p++) {
            uint32_t b[4];
            ldsm4(b, bU + swbase(p * 16 + b_radd, ks * 16 + b_kadd));
            mma16816(acc[2 * p],     ahi, b[0], b[1]);
            mma16816(acc[2 * p + 1], ahi, b[2], b[3]);
            mma16816(acc[2 * p],     alo, b[0], b[1]);
            mma16816(acc[2 * p + 1], alo, b[2], b[3]);
        }
    }
    __syncthreads();          // all warps done reading B slot
}

__global__ __launch_bounds__(NT, 1)
void ode_mma(const float* __restrict__ t_p,
             const float* __restrict__ z,
             const float* __restrict__ context,
             const float* __restrict__ eps,
             const float* __restrict__ W_in, const float* __restrict__ b_in,
             const float* __restrict__ b_h1, const float* __restrict__ b_h2,
             const float* __restrict__ W_out, const float* __restrict__ b_out,
             const float* __restrict__ scale_p,
             float* __restrict__ out)
{
    extern __shared__ unsigned char smb[];
    uint32_t smu = (uint32_t)__cvta_generic_to_shared(smb);
    float* sWout = (float*)(smb + WOUT);

    const int t    = threadIdx.x;
    const int warp = t >> 5;
    const int lane = t & 31;
    const int row0 = blockIdx.x * TILE;
    const float tval   = *t_p;
    const float oscale = *scale_p;

    // ldmatrix lane address parameters
    const int sub = lane >> 3, ro = lane & 7;
    const int a_r    = warp * 16 + ((sub & 1) << 3) + ro;
    const int a_kadd = (sub >> 1) << 3;
    const int b_radd = ((sub >> 1) << 3) + ro;
    const int b_kadd = (sub & 1) << 3;

    // epilogue thread mapping
    const int g  = lane >> 2, qi = lane & 3;
    const int r0 = warp * 16 + g, r1 = r0 + 8;
    const int grow0 = row0 + r0, grow1 = row0 + r1;

    // ---- prefetch B(0); stage input tile; W_out; eps ----
    stageB_async(smb, g_B[0]);
    {
        int r = t >> 1, half = t & 1;
        int grow = row0 + r;
        bool valid = grow < BTOT;
        int kbeg = half * 64, kend = half ? 80 : 64;
        for (int k = kbeg; k < kend; k += 2) {
            float v0 = 0.0f, v1 = 0.0f;
            if (valid) {
                v0 = (k < NDIM) ? z[grow * NDIM + k]
                   : (k < NIN - 1) ? __ldg(context + grow * NCOND + (k - NDIM))
                   : (k == NIN - 1) ? tval : 0.0f;
                int k1 = k + 1;
                v1 = (k1 < NDIM) ? z[grow * NDIM + k1]
                   : (k1 < NIN - 1) ? __ldg(context + grow * NCOND + (k1 - NDIM))
                   : (k1 == NIN - 1) ? tval : 0.0f;
            }
            split_store(smb, X_HI, X_LO, r, k, v0, v1);
        }
    }
    for (int idx = t; idx < NHID * NDIM; idx += NT) sWout[idx] = __ldg(W_out + idx);

    float ep0[3], ep1[3];
#pragma unroll
    for (int d = 0; d < 3; d++) {
        ep0[d] = (grow0 < BTOT) ? __ldg(eps + grow0 * NDIM + d) : 0.0f;
        ep1[d] = (grow1 < BTOT) ? __ldg(eps + grow1 * NDIM + d) : 0.0f;
    }
    CPA_WAIT0(); __syncthreads();

    float acc[16][4];

    // ==== L1: h1 = tanh(in @ W_in + b_in) ====
    run_gemm<5>(smb, smu, X_HI, X_LO, a_r, a_kadd, b_radd, b_kadd, acc);
    stageB_async(smb, g_B[1]);
#pragma unroll
    for (int p = 0; p < 16; p++) {
        int c = p * 8 + qi * 2;
        float b0 = __ldg(b_in + c), b1 = __ldg(b_in + c + 1);
        split_store(smb, H1_HI, H1_LO, r0, c, ftanh(acc[p][0] + b0), ftanh(acc[p][1] + b1));
        split_store(smb, H1_HI, H1_LO, r1, c, ftanh(acc[p][2] + b0), ftanh(acc[p][3] + b1));
    }
    CPA_WAIT0(); __syncthreads();

    // ==== L2: h2 = tanh(h1 @ W_h1 + b_h1) ====
    run_gemm<8>(smb, smu, H1_HI, H1_LO, a_r, a_kadd, b_radd, b_kadd, acc);
    stageB_async(smb, g_B[2]);
#pragma unroll
    for (int p = 0; p < 16; p++) {
        int c = p * 8 + qi * 2;
        float b0 = __ldg(b_h1 + c), b1 = __ldg(b_h1 + c + 1);
        split_store(smb, H2_HI, H2_LO, r0, c, ftanh(acc[p][0] + b0), ftanh(acc[p][1] + b1));
        split_store(smb, H2_HI, H2_LO, r1, c, ftanh(acc[p][2] + b0), ftanh(acc[p][3] + b1));
    }
    CPA_WAIT0(); __syncthreads();

    // ==== L3: h3 in regs; f per-row; g3 -> X ====
    run_gemm<8>(smb, smu, H2_HI, H2_LO, a_r, a_kadd, b_radd, b_kadd, acc);
    stageB_async(smb, g_B[3]);
    {
        float pf0[3] = {0, 0, 0}, pf1[3] = {0, 0, 0};
#pragma unroll
        for (int p = 0; p < 16; p++) {
            int c = p * 8 + qi * 2;
            float b0 = __ldg(b_h2 + c), b1 = __ldg(b_h2 + c + 1);
            float h00 = ftanh(acc[p][0] + b0), h01 = ftanh(acc[p][1] + b1);
            float h10 = ftanh(acc[p][2] + b0), h11 = ftanh(acc[p][3] + b1);
            float wa0 = sWout[c * 3 + 0], wa1 = sWout[c * 3 + 1], wa2 = sWout[c * 3 + 2];
            float wb0 = sWout[c * 3 + 3], wb1 = sWout[c * 3 + 4], wb2 = sWout[c * 3 + 5];
            pf0[0] += h00 * wa0 + h01 * wb0;
            pf0[1] += h00 * wa1 + h01 * wb1;
            pf0[2] += h00 * wa2 + h01 * wb2;
            pf1[0] += h10 * wa0 + h11 * wb0;
            pf1[1] += h10 * wa1 + h11 * wb1;
            pf1[2] += h10 * wa2 + h11 * wb2;
            float s0a = ep0[0] * wa0 + ep0[1] * wa1 + ep0[2] * wa2;
            float s0b = ep0[0] * wb0 + ep0[1] * wb1 + ep0[2] * wb2;
            float s1a = ep1[0] * wa0 + ep1[1] * wa1 + ep1[2] * wa2;
            float s1b = ep1[0] * wb0 + ep1[1] * wb1 + ep1[2] * wb2;
            split_store(smb, X_HI, X_LO, r0, c,
                        s0a * oscale * (1.0f - h00 * h00),
                        s0b * oscale * (1.0f - h01 * h01));
            split_store(smb, X_HI, X_LO, r1, c,
                        s1a * oscale * (1.0f - h10 * h10),
                        s1b * oscale * (1.0f - h11 * h11));
        }
#pragma unroll
        for (int d = 0; d < 3; d++) {
            pf0[d] += __shfl_down_sync(0xffffffffu, pf0[d], 2, 4);
            pf0[d] += __shfl_down_sync(0xffffffffu, pf0[d], 1, 4);
            pf1[d] += __shfl_down_sync(0xffffffffu, pf1[d], 2, 4);
            pf1[d] += __shfl_down_sync(0xffffffffu, pf1[d], 1, 4);
        }
        if (qi == 0) {
#pragma unroll
            for (int d = 0; d < 3; d++) {
                if (grow0 < BTOT) out[grow0 * NDIM + d] = (pf0[d] + __ldg(b_out + d)) * oscale;
                if (grow1 < BTOT) out[grow1 * NDIM + d] = (pf1[d] + __ldg(b_out + d)) * oscale;
            }
        }
    }
    CPA_WAIT0(); __syncthreads();

    // ==== g2 = (g3 @ W_h2) * (1 - h2^2) -> X (rows warp-private) ====
    run_gemm<8>(smb, smu, X_HI, X_LO, a_r, a_kadd, b_radd, b_kadd, acc);
    stageB_async(smb, g_B[4]);
#pragma unroll
    for (int p = 0; p < 16; p++) {
        int c = p * 8 + qi * 2;
        float h00, h01, h10, h11;
        ld_pair(smb, H2_HI, H2_LO, r0, c, h00, h01);
        ld_pair(smb, H2_HI, H2_LO, r1, c, h10, h11);
        split_store(smb, X_HI, X_LO, r0, c,
                    acc[p][0] * (1.0f - h00 * h00), acc[p][1] * (1.0f - h01 * h01));
        split_store(smb, X_HI, X_LO, r1, c,
                    acc[p][2] * (1.0f - h10 * h10), acc[p][3] * (1.0f - h11 * h11));
    }
    CPA_WAIT0(); __syncthreads();

    // ==== g1 = (g2 @ W_h1) * (1 - h1^2); gz; neg_div ====
    run_gemm<8>(smb, smu, X_HI, X_LO, a_r, a_kadd, b_radd, b_kadd, acc);
    {
        float gz0[3] = {0, 0, 0}, gz1[3] = {0, 0, 0};
#pragma unroll
        for (int p = 0; p < 16; p++) {
            int c = p * 8 + qi * 2;
            float h00, h01, h10, h11;
            ld_pair(smb, H1_HI, H1_LO, r0, c, h00, h01);
            ld_pair(smb, H1_HI, H1_LO, r1, c, h10, h11);
            float g00 = acc[p][0] * (1.0f - h00 * h00);
            float g01 = acc[p][1] * (1.0f - h01 * h01);
            float g10 = acc[p][2] * (1.0f - h10 * h10);
            float g11 = acc[p][3] * (1.0f - h11 * h11);
#pragma unroll
            for (int d = 0; d < 3; d++) {
                float w0 = __ldg(W_in + d * NHID + c);
                float w1 = __ldg(W_in + d * NHID + c + 1);
                gz0[d] += g00 * w0 + g01 * w1;
                gz1[d] += g10 * w0 + g11 * w1;
            }
        }
#pragma unroll
        for (int d = 0; d < 3; d++) {
            gz0[d] += __shfl_down_sync(0xffffffffu, gz0[d], 2, 4);
            gz0[d] += __shfl_down_sync(0xffffffffu, gz0[d], 1, 4);
            gz1[d] += __shfl_down_sync(0xffffffffu, gz1[d], 2, 4);
            gz1[d] += __shfl_down_sync(0xffffffffu, gz1[d], 1, 4);
        }
        if (qi == 0) {
            if (grow0 < BTOT)
                out[BTOT * NDIM + grow0] = -(gz0[0] * ep0[0] + gz0[1] * ep0[1] + gz0[2] * ep0[2]);
            if (grow1 < BTOT)
                out[BTOT * NDIM + grow1] = -(gz1[0] * ep1[0] + gz1[1] * ep1[1] + gz1[2] * ep1[2]);
        }
    }
}

extern "C" void kernel_launch(void* const* d_in, const int* in_sizes, int n_in,
                              void* d_out, int out_size) {
    const float* t_p     = (const float*)d_in[0];
    const float* z       = (const float*)d_in[1];
    const float* context = (const float*)d_in[3];
    const float* eps     = (const float*)d_in[4];
    const float* W_in    = (const float*)d_in[5];
    const float* b_in    = (const float*)d_in[6];
    const float* W_h1    = (const float*)d_in[7];
    const float* b_h1    = (const float*)d_in[8];
    const float* W_h2    = (const float*)d_in[9];
    const float* b_h2    = (const float*)d_in[10];
    const float* W_out   = (const float*)d_in[11];
    const float* b_out   = (const float*)d_in[12];
    const float* scale_p = (const float*)d_in[13];
    float* out = (float*)d_out;

    cudaFuncSetAttribute(ode_mma, cudaFuncAttributeMaxDynamicSharedMemorySize, SM_TOT);

    prep_k<<<(5 * NHID * NHID + 255) / 256, 256>>>(W_in, W_h1, W_h2);

    const int grid = (BTOT + TILE - 1) / TILE;   // 3907
    ode_mma<<<grid, NT, SM_TOT>>>(t_p, z, context, eps,
                                  W_in, b_in, b_h1, b_h2,
                                  W_out, b_out, scale_p, out);
}

// round 15
// speedup vs baseline: 3.7746x; 1.0888x over previous
#include <cuda_runtime.h>
#include <cuda_fp16.h>
#include <cstdint>

#define BTOT   500000
#define NDIM   3
#define NCOND  64
#define NHID   128
#define NIN    68
#define TILE   64
#define NT     128

// SMEM byte offsets (per CTA: 112 KB)
#define X_HI   0
#define X_LO   16384
#define H1_HI  32768
#define H1_LO  49152
#define H2_HI  65536
#define H2_LO  81920
#define B_SL   98304           // 16KB half-K weight slot
#define SM_TOT 114688

// Pre-swizzled fp16 weight operands, split in K-halves:
// which: 0=W_in^T(padK) 1=W_h1^T 2=W_h2^T 3=W_h2 4=W_h1 ; [which][khalf][16KB]
__device__ __align__(16) unsigned char g_B[5][2][16384];

// A layout (full K=128): row stride 256B, 16-chunk XOR swizzle.
__device__ __forceinline__ int swoff(int r, int k) {
    return r * 256 + ((((k >> 3) ^ (r & 7)) & 15) << 4) + (k & 7) * 2;
}
__device__ __forceinline__ uint32_t swbase(int r, int kb) {
    return (uint32_t)(r * 256 + ((((kb >> 3) ^ (r & 7)) & 15) << 4));
}
// B half layout (K=64): row stride 128B, 8-chunk XOR swizzle.
__device__ __forceinline__ int swoffB(int r, int k) {
    return r * 128 + ((((k >> 3) ^ (r & 7)) & 7) << 4) + (k & 7) * 2;
}
__device__ __forceinline__ uint32_t swbaseB(int r, int kb) {
    return (uint32_t)(r * 128 + ((((kb >> 3) ^ (r & 7)) & 7) << 4));
}

__global__ void prep_k(const float* __restrict__ Wi, const float* __restrict__ W1,
                       const float* __restrict__ W2) {
    int idx = blockIdx.x * blockDim.x + threadIdx.x;
    if (idx >= 5 * NHID * NHID) return;
    int t = idx >> 14, e = idx & 16383, n = e >> 7, k = e & 127;
    float v;
    switch (t) {
        case 0:  v = (k < NIN) ? Wi[k * NHID + n] : 0.0f; break;  // fwd L1
        case 1:  v = W1[k * NHID + n]; break;                     // fwd L2
        case 2:  v = W2[k * NHID + n]; break;                     // fwd L3
        case 3:  v = W2[n * NHID + k]; break;                     // bwd g2
        default: v = W1[n * NHID + k]; break;                     // bwd g1
    }
    *(unsigned short*)(g_B[t][k >> 6] + swoffB(n, k & 63)) =
        __half_as_ushort(__float2half_rn(v));
}

__device__ __forceinline__ float ftanh(float x) {
    float e = __expf(2.0f * x);
    return __fdividef(e - 1.0f, e + 1.0f);
}

__device__ __forceinline__ void ldsm4(uint32_t a[4], uint32_t addr) {
    asm volatile("ldmatrix.sync.aligned.m8n8.x4.shared.b16 {%0,%1,%2,%3}, [%4];"
        : "=r"(a[0]), "=r"(a[1]), "=r"(a[2]), "=r"(a[3]) : "r"(addr));
}
__device__ __forceinline__ void mma16816(float d[4], const uint32_t a[4],
                                         uint32_t b0, uint32_t b1) {
    asm volatile("mma.sync.aligned.m16n8k16.row.col.f32.f16.f16.f32 "
        "{%0,%1,%2,%3}, {%4,%5,%6,%7}, {%8,%9}, {%0,%1,%2,%3};"
        : "+f"(d[0]), "+f"(d[1]), "+f"(d[2]), "+f"(d[3])
        : "r"(a[0]), "r"(a[1]), "r"(a[2]), "r"(a[3]), "r"(b0), "r"(b1));
}

__device__ __forceinline__ void split_store(unsigned char* smb, int hiB, int loB,
                                            int r, int c, float v0, float v1) {
    __half h0 = __float2half_rn(v0), h1 = __float2half_rn(v1);
    __half l0 = __float2half_rn(v0 - __half2float(h0));
    __half l1 = __float2half_rn(v1 - __half2float(h1));
    int o = swoff(r, c);
    *(uint32_t*)(smb + hiB + o) =
        (uint32_t)__half_as_ushort(h0) | ((uint32_t)__half_as_ushort(h1) << 16);
    *(uint32_t*)(smb + loB + o) =
        (uint32_t)__half_as_ushort(l0) | ((uint32_t)__half_as_ushort(l1) << 16);
}
__device__ __forceinline__ void ld_pair(const unsigned char* smb, int hiB, int loB,
                                        int r, int c, float& v0, float& v1) {
    int o = swoff(r, c);
    uint32_t wh = *(const uint32_t*)(smb + hiB + o);
    uint32_t wl = *(const uint32_t*)(smb + loB + o);
    v0 = __half2float(__ushort_as_half((unsigned short)(wh & 0xFFFFu)))
       + __half2float(__ushort_as_half((unsigned short)(wl & 0xFFFFu)));
    v1 = __half2float(__ushort_as_half((unsigned short)(wh >> 16)))
       + __half2float(__ushort_as_half((unsigned short)(wl >> 16)));
}

__device__ __forceinline__ void stageB_async(unsigned char* smb, const unsigned char* src) {
    uint32_t s = (uint32_t)__cvta_generic_to_shared(smb + B_SL);
    for (int i = threadIdx.x; i < 1024; i += NT)
        asm volatile("cp.async.cg.shared.global [%0], [%1], 16;"
                     :: "r"(s + i * 16), "l"(src + i * 16));
    asm volatile("cp.async.commit_group;");
}
#define CPA_WAIT0() asm volatile("cp.async.wait_group 0;")

// Partial K sweep: acc += Ahi*B + Alo*B for ks in [0,N_KS) of the staged half.
// ksA0 = A-side k chunk offset (0 or 4).
template<int N_KS, bool ZERO>
__device__ __forceinline__ void sweep(uint32_t aHiU, uint32_t aLoU, uint32_t bU,
                                      int ksA0, int a_r, int a_kadd,
                                      int b_radd, int b_kadd, float acc[16][4]) {
    if (ZERO) {
#pragma unroll
        for (int p = 0; p < 16; p++)
#pragma unroll
            for (int q = 0; q < 4; q++) acc[p][q] = 0.0f;
    }
#pragma unroll
    for (int i = 0; i < N_KS; i++) {
        uint32_t ahi[4], alo[4];
        ldsm4(ahi, aHiU + swbase(a_r, (ksA0 + i) * 16 + a_kadd));
        ldsm4(alo, aLoU + swbase(a_r, (ksA0 + i) * 16 + a_kadd));
#pragma unroll
        for (int p = 0; p < 8; p++) {
            uint32_t b[4];
            ldsm4(b, bU + swbaseB(p * 16 + b_radd, i * 16 + b_kadd));
            mma16816(acc[2 * p],     ahi, b[0], b[1]);
            mma16816(acc[2 * p + 1], ahi, b[2], b[3]);
            mma16816(acc[2 * p],     alo, b[0], b[1]);
            mma16816(acc[2 * p + 1], alo, b[2], b[3]);
        }
    }
}

// Full GEMM with half-K staged B: on entry half0 staged+synced.
// KS1 = ks count in half1 (1 for L1, 4 otherwise).
#define GEMM(bIdx, KS1, aHiOff, aLoOff)                                        \
    sweep<4, true>(smu + (aHiOff), smu + (aLoOff), smu + B_SL, 0,              \
                   a_r, a_kadd, b_radd, b_kadd, acc);                          \
    __syncthreads();                                                           \
    stageB_async(smb, g_B[bIdx][1]);                                           \
    CPA_WAIT0(); __syncthreads();                                              \
    sweep<KS1, false>(smu + (aHiOff), smu + (aLoOff), smu + B_SL, 4,           \
                      a_r, a_kadd, b_radd, b_kadd, acc);                       \
    __syncthreads();

__global__ __launch_bounds__(NT, 2)
void ode_mma(const float* __restrict__ t_p,
             const float* __restrict__ z,
             const float* __restrict__ context,
             const float* __restrict__ eps,
             const float* __restrict__ W_in, const float* __restrict__ b_in,
             const float* __restrict__ b_h1, const float* __restrict__ b_h2,
             const float* __restrict__ W_out, const float* __restrict__ b_out,
             const float* __restrict__ scale_p,
             float* __restrict__ out)
{
    extern __shared__ unsigned char smb[];
    uint32_t smu = (uint32_t)__cvta_generic_to_shared(smb);

    const int t    = threadIdx.x;
    const int warp = t >> 5;
    const int lane = t & 31;
    const int row0 = blockIdx.x * TILE;
    const float tval   = *t_p;
    const float oscale = *scale_p;

    // ldmatrix lane address parameters
    const int sub = lane >> 3, ro = lane & 7;
    const int a_r    = warp * 16 + ((sub & 1) << 3) + ro;
    const int a_kadd = (sub >> 1) << 3;
    const int b_radd = ((sub >> 1) << 3) + ro;
    const int b_kadd = (sub & 1) << 3;

    // epilogue thread mapping
    const int g  = lane >> 2, qi = lane & 3;
    const int r0 = warp * 16 + g, r1 = r0 + 8;
    const int grow0 = row0 + r0, grow1 = row0 + r1;

    // ---- prefetch B(0,half0); stage input tile; eps ----
    stageB_async(smb, g_B[0][0]);
    {
        int r = t >> 1, half = t & 1;
        int grow = row0 + r;
        bool valid = grow < BTOT;
        int kbeg = half * 64, kend = half ? 80 : 64;
        for (int k = kbeg; k < kend; k += 2) {
            float v0 = 0.0f, v1 = 0.0f;
            if (valid) {
                v0 = (k < NDIM) ? z[grow * NDIM + k]
                   : (k < NIN - 1) ? __ldg(context + grow * NCOND + (k - NDIM))
                   : (k == NIN - 1) ? tval : 0.0f;
                int k1 = k + 1;
                v1 = (k1 < NDIM) ? z[grow * NDIM + k1]
                   : (k1 < NIN - 1) ? __ldg(context + grow * NCOND + (k1 - NDIM))
                   : (k1 == NIN - 1) ? tval : 0.0f;
            }
            split_store(smb, X_HI, X_LO, r, k, v0, v1);
        }
    }
    float ep0[3], ep1[3];
#pragma unroll
    for (int d = 0; d < 3; d++) {
        ep0[d] = (grow0 < BTOT) ? __ldg(eps + grow0 * NDIM + d) : 0.0f;
        ep1[d] = (grow1 < BTOT) ? __ldg(eps + grow1 * NDIM + d) : 0.0f;
    }
    CPA_WAIT0(); __syncthreads();

    float acc[16][4];

    // ==== L1: h1 = tanh(in @ W_in + b_in) ====   (K = 80: 4 + 1 ksteps)
    GEMM(0, 1, X_HI, X_LO);
    stageB_async(smb, g_B[1][0]);
#pragma unroll
    for (int p = 0; p < 16; p++) {
        int c = p * 8 + qi * 2;
        float b0 = __ldg(b_in + c), b1 = __ldg(b_in + c + 1);
        split_store(smb, H1_HI, H1_LO, r0, c, ftanh(acc[p][0] + b0), ftanh(acc[p][1] + b1));
        split_store(smb, H1_HI, H1_LO, r1, c, ftanh(acc[p][2] + b0), ftanh(acc[p][3] + b1));
    }
    CPA_WAIT0(); __syncthreads();

    // ==== L2: h2 = tanh(h1 @ W_h1 + b_h1) ====
    GEMM(1, 4, H1_HI, H1_LO);
    stageB_async(smb, g_B[2][0]);
#pragma unroll
    for (int p = 0; p < 16; p++) {
        int c = p * 8 + qi * 2;
        float b0 = __ldg(b_h1 + c), b1 = __ldg(b_h1 + c + 1);
        split_store(smb, H2_HI, H2_LO, r0, c, ftanh(acc[p][0] + b0), ftanh(acc[p][1] + b1));
        split_store(smb, H2_HI, H2_LO, r1, c, ftanh(acc[p][2] + b0), ftanh(acc[p][3] + b1));
    }
    CPA_WAIT0(); __syncthreads();

    // ==== L3: h3 in regs; f per-row; g3 -> X ====
    GEMM(2, 4, H2_HI, H2_LO);
    stageB_async(smb, g_B[3][0]);
    {
        float pf0[3] = {0, 0, 0}, pf1[3] = {0, 0, 0};
#pragma unroll
        for (int p = 0; p < 16; p++) {
            int c = p * 8 + qi * 2;
            float b0 = __ldg(b_h2 + c), b1 = __ldg(b_h2 + c + 1);
            float h00 = ftanh(acc[p][0] + b0), h01 = ftanh(acc[p][1] + b1);
            float h10 = ftanh(acc[p][2] + b0), h11 = ftanh(acc[p][3] + b1);
            float wa0 = __ldg(W_out + c * 3 + 0), wa1 = __ldg(W_out + c * 3 + 1),
                  wa2 = __ldg(W_out + c * 3 + 2);
            float wb0 = __ldg(W_out + c * 3 + 3), wb1 = __ldg(W_out + c * 3 + 4),
                  wb2 = __ldg(W_out + c * 3 + 5);
            pf0[0] += h00 * wa0 + h01 * wb0;
            pf0[1] += h00 * wa1 + h01 * wb1;
            pf0[2] += h00 * wa2 + h01 * wb2;
            pf1[0] += h10 * wa0 + h11 * wb0;
            pf1[1] += h10 * wa1 + h11 * wb1;
            pf1[2] += h10 * wa2 + h11 * wb2;
            float s0a = ep0[0] * wa0 + ep0[1] * wa1 + ep0[2] * wa2;
            float s0b = ep0[0] * wb0 + ep0[1] * wb1 + ep0[2] * wb2;
            float s1a = ep1[0] * wa0 + ep1[1] * wa1 + ep1[2] * wa2;
            float s1b = ep1[0] * wb0 + ep1[1] * wb1 + ep1[2] * wb2;
            split_store(smb, X_HI, X_LO, r0, c,
                        s0a * oscale * (1.0f - h00 * h00),
                        s0b * oscale * (1.0f - h01 * h01));
            split_store(smb, X_HI, X_LO, r1, c,
                        s1a * oscale * (1.0f - h10 * h10),
                        s1b * oscale * (1.0f - h11 * h11));
        }
#pragma unroll
        for (int d = 0; d < 3; d++) {
            pf0[d] += __shfl_down_sync(0xffffffffu, pf0[d], 2, 4);
            pf0[d] += __shfl_down_sync(0xffffffffu, pf0[d], 1, 4);
            pf1[d] += __shfl_down_sync(0xffffffffu, pf1[d], 2, 4);
            pf1[d] += __shfl_down_sync(0xffffffffu, pf1[d], 1, 4);
        }
        if (qi == 0) {
#pragma unroll
            for (int d = 0; d < 3; d++) {
                if (grow0 < BTOT) out[grow0 * NDIM + d] = (pf0[d] + __ldg(b_out + d)) * oscale;
                if (grow1 < BTOT) out[grow1 * NDIM + d] = (pf1[d] + __ldg(b_out + d)) * oscale;
            }
        }
    }
    CPA_WAIT0(); __syncthreads();

    // ==== g2 = (g3 @ W_h2) * (1 - h2^2) -> X (rows warp-private) ====
    GEMM(3, 4, X_HI, X_LO);
    stageB_async(smb, g_B[4][0]);
#pragma unroll
    for (int p = 0; p < 16; p++) {
        int c = p * 8 + qi * 2;
        float h00, h01, h10, h11;
        ld_pair(smb, H2_HI, H2_LO, r0, c, h00, h01);
        ld_pair(smb, H2_HI, H2_LO, r1, c, h10, h11);
        split_store(smb, X_HI, X_LO, r0, c,
                    acc[p][0] * (1.0f - h00 * h00), acc[p][1] * (1.0f - h01 * h01));
        split_store(smb, X_HI, X_LO, r1, c,
                    acc[p][2] * (1.0f - h10 * h10), acc[p][3] * (1.0f - h11 * h11));
    }
    CPA_WAIT0(); __syncthreads();

    // ==== g1 = (g2 @ W_h1) * (1 - h1^2); gz; neg_div ====
    GEMM(4, 4, X_HI, X_LO);
    {
        float gz0[3] = {0, 0, 0}, gz1[3] = {0, 0, 0};
#pragma unroll
        for (int p = 0; p < 16; p++) {
            int c = p * 8 + qi * 2;
            float h00, h01, h10, h11;
            ld_pair(smb, H1_HI, H1_LO, r0, c, h00, h01);
            ld_pair(smb, H1_HI, H1_LO, r1, c, h10, h11);
            float g00 = acc[p][0] * (1.0f - h00 * h00);
            float g01 = acc[p][1] * (1.0f - h01 * h01);
            float g10 = acc[p][2] * (1.0f - h10 * h10);
            float g11 = acc[p][3] * (1.0f - h11 * h11);
#pragma unroll
            for (int d = 0; d < 3; d++) {
                float w0 = __ldg(W_in + d * NHID + c);
                float w1 = __ldg(W_in + d * NHID + c + 1);
                gz0[d] += g00 * w0 + g01 * w1;
                gz1[d] += g10 * w0 + g11 * w1;
            }
        }
#pragma unroll
        for (int d = 0; d < 3; d++) {
            gz0[d] += __shfl_down_sync(0xffffffffu, gz0[d], 2, 4);
            gz0[d] += __shfl_down_sync(0xffffffffu, gz0[d], 1, 4);
            gz1[d] += __shfl_down_sync(0xffffffffu, gz1[d], 2, 4);
            gz1[d] += __shfl_down_sync(0xffffffffu, gz1[d], 1, 4);
        }
        if (qi == 0) {
            if (grow0 < BTOT)
                out[BTOT * NDIM + grow0] = -(gz0[0] * ep0[0] + gz0[1] * ep0[1] + gz0[2] * ep0[2]);
            if (grow1 < BTOT)
                out[BTOT * NDIM + grow1] = -(gz1[0] * ep1[0] + gz1[1] * ep1[1] + gz1[2] * ep1[2]);
        }
    }
}

extern "C" void kernel_launch(void* const* d_in, const int* in_sizes, int n_in,
                              void* d_out, int out_size) {
    const float* t_p     = (const float*)d_in[0];
    const float* z       = (const float*)d_in[1];
    const float* context = (const float*)d_in[3];
    const float* eps     = (const float*)d_in[4];
    const float* W_in    = (const float*)d_in[5];
    const float* b_in    = (const float*)d_in[6];
    const float* W_h1    = (const float*)d_in[7];
    const float* b_h1    = (const float*)d_in[8];
    const float* W_h2    = (const float*)d_in[9];
    const float* b_h2    = (const float*)d_in[10];
    const float* W_out   = (const float*)d_in[11];
    const float* b_out   = (const float*)d_in[12];
    const float* scale_p = (const float*)d_in[13];
    float* out = (float*)d_out;

    cudaFuncSetAttribute(ode_mma, cudaFuncAttributeMaxDynamicSharedMemorySize, SM_TOT);

    prep_k<<<(5 * NHID * NHID + 255) / 256, 256>>>(W_in, W_h1, W_h2);

    const int grid = (BTOT + TILE - 1) / TILE;   // 7813
    ode_mma<<<grid, NT, SM_TOT>>>(t_p, z, context, eps,
                                  W_in, b_in, b_h1, b_h2,
                                  W_out, b_out, scale_p, out);
}

// round 16
// speedup vs baseline: 4.9967x; 1.3238x over previous
#include <cuda_runtime.h>
#include <cuda_fp16.h>
#include <cstdint>

#define BTOT   500000
#define NDIM   3
#define NCOND  64
#define NHID   128
#define NIN    68
#define TILE   64
#define NT     128

// SMEM byte offsets (per CTA: 112 KB)
#define X_HI   0
#define X_LO   16384
#define H1_HI  32768
#define H1_LO  49152
#define H2_HI  65536
#define H2_LO  81920
#define B_SL   98304           // 16KB half-K weight slot
#define SM_TOT 114688

// Pre-swizzled fp16 weight operands, split in K-halves:
// which: 0=W_in^T(padK, input rows permuted: z,z,z,t,ctx...) 1=W_h1^T 2=W_h2^T 3=W_h2 4=W_h1
__device__ __align__(16) unsigned char g_B[5][2][16384];

// A layout (full K=128): row stride 256B, 16-chunk XOR swizzle.
__device__ __forceinline__ int swoff(int r, int k) {
    return r * 256 + ((((k >> 3) ^ (r & 7)) & 15) << 4) + (k & 7) * 2;
}
__device__ __forceinline__ uint32_t swbase(int r, int kb) {
    return (uint32_t)(r * 256 + ((((kb >> 3) ^ (r & 7)) & 15) << 4));
}
// B half layout (K=64): row stride 128B, 8-chunk XOR swizzle.
__device__ __forceinline__ int swoffB(int r, int k) {
    return r * 128 + ((((k >> 3) ^ (r & 7)) & 7) << 4) + (k & 7) * 2;
}
__device__ __forceinline__ uint32_t swbaseB(int r, int kb) {
    return (uint32_t)(r * 128 + ((((kb >> 3) ^ (r & 7)) & 7) << 4));
}

__global__ void prep_k(const float* __restrict__ Wi, const float* __restrict__ W1,
                       const float* __restrict__ W2) {
    int idx = blockIdx.x * blockDim.x + threadIdx.x;
    if (idx >= 5 * NHID * NHID) return;
    int t = idx >> 14, e = idx & 16383, n = e >> 7, k = e & 127;
    float v;
    switch (t) {
        case 0: {   // fwd L1, input rows permuted: 0..2=z, 3=t(orig 67), 4..67=ctx(orig k-1)
            if (k < NIN) {
                int kk = (k < 3) ? k : (k == 3 ? 67 : k - 1);
                v = Wi[kk * NHID + n];
            } else v = 0.0f;
            break;
        }
        case 1:  v = W1[k * NHID + n]; break;                     // fwd L2
        case 2:  v = W2[k * NHID + n]; break;                     // fwd L3
        case 3:  v = W2[n * NHID + k]; break;                     // bwd g2
        default: v = W1[n * NHID + k]; break;                     // bwd g1
    }
    *(unsigned short*)(g_B[t][k >> 6] + swoffB(n, k & 63)) =
        __half_as_ushort(__float2half_rn(v));
}

__device__ __forceinline__ float ftanh(float x) {
    float e = __expf(2.0f * x);
    return __fdividef(e - 1.0f, e + 1.0f);
}

__device__ __forceinline__ void ldsm4(uint32_t a[4], uint32_t addr) {
    asm volatile("ldmatrix.sync.aligned.m8n8.x4.shared.b16 {%0,%1,%2,%3}, [%4];"
        : "=r"(a[0]), "=r"(a[1]), "=r"(a[2]), "=r"(a[3]) : "r"(addr));
}
__device__ __forceinline__ void mma16816(float d[4], const uint32_t a[4],
                                         uint32_t b0, uint32_t b1) {
    asm volatile("mma.sync.aligned.m16n8k16.row.col.f32.f16.f16.f32 "
        "{%0,%1,%2,%3}, {%4,%5,%6,%7}, {%8,%9}, {%0,%1,%2,%3};"
        : "+f"(d[0]), "+f"(d[1]), "+f"(d[2]), "+f"(d[3])
        : "r"(a[0]), "r"(a[1]), "r"(a[2]), "r"(a[3]), "r"(b0), "r"(b1));
}

// Packed conversions: ~5 instr per value-pair.
__device__ __forceinline__ void split_store(unsigned char* smb, int hiB, int loB,
                                            int r, int c, float v0, float v1) {
    __half2 h = __floats2half2_rn(v0, v1);
    float2 hf = __half22float2(h);
    __half2 l = __floats2half2_rn(v0 - hf.x, v1 - hf.y);
    int o = swoff(r, c);
    *(__half2*)(smb + hiB + o) = h;
    *(__half2*)(smb + loB + o) = l;
}
__device__ __forceinline__ void ld_pair(const unsigned char* smb, int hiB, int loB,
                                        int r, int c, float& v0, float& v1) {
    int o = swoff(r, c);
    float2 fh = __half22float2(*(const __half2*)(smb + hiB + o));
    float2 fl = __half22float2(*(const __half2*)(smb + loB + o));
    v0 = fh.x + fl.x;
    v1 = fh.y + fl.y;
}

__device__ __forceinline__ void stageB_async(unsigned char* smb, const unsigned char* src) {
    uint32_t s = (uint32_t)__cvta_generic_to_shared(smb + B_SL);
    for (int i = threadIdx.x; i < 1024; i += NT)
        asm volatile("cp.async.cg.shared.global [%0], [%1], 16;"
                     :: "r"(s + i * 16), "l"(src + i * 16));
    asm volatile("cp.async.commit_group;");
}
#define CPA_WAIT0() asm volatile("cp.async.wait_group 0;")

template<int N_KS, bool ZERO>
__device__ __forceinline__ void sweep(uint32_t aHiU, uint32_t aLoU, uint32_t bU,
                                      int ksA0, int a_r, int a_kadd,
                                      int b_radd, int b_kadd, float acc[16][4]) {
    if (ZERO) {
#pragma unroll
        for (int p = 0; p < 16; p++)
#pragma unroll
            for (int q = 0; q < 4; q++) acc[p][q] = 0.0f;
    }
#pragma unroll
    for (int i = 0; i < N_KS; i++) {
        uint32_t ahi[4], alo[4];
        ldsm4(ahi, aHiU + swbase(a_r, (ksA0 + i) * 16 + a_kadd));
        ldsm4(alo, aLoU + swbase(a_r, (ksA0 + i) * 16 + a_kadd));
#pragma unroll
        for (int p = 0; p < 8; p++) {
            uint32_t b[4];
            ldsm4(b, bU + swbaseB(p * 16 + b_radd, i * 16 + b_kadd));
            mma16816(acc[2 * p],     ahi, b[0], b[1]);
            mma16816(acc[2 * p + 1], ahi, b[2], b[3]);
            mma16816(acc[2 * p],     alo, b[0], b[1]);
            mma16816(acc[2 * p + 1], alo, b[2], b[3]);
        }
    }
}

#define GEMM(bIdx, KS1, aHiOff, aLoOff)                                        \
    sweep<4, true>(smu + (aHiOff), smu + (aLoOff), smu + B_SL, 0,              \
                   a_r, a_kadd, b_radd, b_kadd, acc);                          \
    __syncthreads();                                                           \
    stageB_async(smb, g_B[bIdx][1]);                                           \
    CPA_WAIT0(); __syncthreads();                                              \
    sweep<KS1, false>(smu + (aHiOff), smu + (aLoOff), smu + B_SL, 4,           \
                      a_r, a_kadd, b_radd, b_kadd, acc);                       \
    __syncthreads();

__global__ __launch_bounds__(NT, 2)
void ode_mma(const float* __restrict__ t_p,
             const float* __restrict__ z,
             const float* __restrict__ context,
             const float* __restrict__ eps,
             const float* __restrict__ W_in, const float* __restrict__ b_in,
             const float* __restrict__ b_h1, const float* __restrict__ b_h2,
             const float* __restrict__ W_out, const float* __restrict__ b_out,
             const float* __restrict__ scale_p,
             float* __restrict__ out)
{
    extern __shared__ unsigned char smb[];
    uint32_t smu = (uint32_t)__cvta_generic_to_shared(smb);

    const int t    = threadIdx.x;
    const int warp = t >> 5;
    const int lane = t & 31;
    const int row0 = blockIdx.x * TILE;
    const float tval   = *t_p;
    const float oscale = *scale_p;

    const int sub = lane >> 3, ro = lane & 7;
    const int a_r    = warp * 16 + ((sub & 1) << 3) + ro;
    const int a_kadd = (sub >> 1) << 3;
    const int b_radd = ((sub >> 1) << 3) + ro;
    const int b_kadd = (sub & 1) << 3;

    const int g  = lane >> 2, qi = lane & 3;
    const int r0 = warp * 16 + g, r1 = r0 + 8;
    const int grow0 = row0 + r0, grow1 = row0 + r1;

    // ---- prefetch B(0,half0); stage input tile (permuted features) ----
    stageB_async(smb, g_B[0][0]);

    // z + t columns (k=0..3): threads 0..63, one row each
    if (t < TILE) {
        int grow = row0 + t;
        float z0 = 0.0f, z1 = 0.0f, z2 = 0.0f;
        if (grow < BTOT) {
            z0 = z[grow * NDIM + 0];
            z1 = z[grow * NDIM + 1];
            z2 = z[grow * NDIM + 2];
        }
        split_store(smb, X_HI, X_LO, t, 0, z0, z1);
        split_store(smb, X_HI, X_LO, t, 2, z2, (grow < BTOT) ? tval : 0.0f);
    }
    // context (k=4..67): coalesced float4; 64 rows x 16 float4 = 1024 chunks
    {
#pragma unroll
        for (int i = 0; i < 8; i++) {
            int fidx = t + i * NT;
            int r = fidx >> 4, c4 = fidx & 15;
            int grow = row0 + r;
            float4 v = make_float4(0.0f, 0.0f, 0.0f, 0.0f);
            if (grow < BTOT)
                v = __ldg((const float4*)(context + grow * NCOND) + c4);
            int k = 4 + 4 * c4;
            split_store(smb, X_HI, X_LO, r, k,     v.x, v.y);
            split_store(smb, X_HI, X_LO, r, k + 2, v.z, v.w);
        }
    }
    // zero pad k=68..79: 64 rows x 6 pairs = 384
#pragma unroll
    for (int i = 0; i < 3; i++) {
        int idx = t + i * NT;
        int r = idx / 6, pr = idx - r * 6;
        split_store(smb, X_HI, X_LO, r, 68 + 2 * pr, 0.0f, 0.0f);
    }

    float ep0[3], ep1[3];
#pragma unroll
    for (int d = 0; d < 3; d++) {
        ep0[d] = (grow0 < BTOT) ? __ldg(eps + grow0 * NDIM + d) : 0.0f;
        ep1[d] = (grow1 < BTOT) ? __ldg(eps + grow1 * NDIM + d) : 0.0f;
    }

    // De-phase co-resident CTA pairs (first wave only): odd CTAs skew half a phase.
    if ((blockIdx.x & 1) && blockIdx.x < 296) {
        long long t0 = clock64();
        while (clock64() - t0 < 4000) { }
    }
    CPA_WAIT0(); __syncthreads();

    float acc[16][4];

    // ==== L1: h1 = tanh(in @ W_in + b_in) ====   (K = 80: 4 + 1 ksteps)
    GEMM(0, 1, X_HI, X_LO);
    stageB_async(smb, g_B[1][0]);
#pragma unroll
    for (int p = 0; p < 16; p++) {
        int c = p * 8 + qi * 2;
        float b0 = __ldg(b_in + c), b1 = __ldg(b_in + c + 1);
        split_store(smb, H1_HI, H1_LO, r0, c, ftanh(acc[p][0] + b0), ftanh(acc[p][1] + b1));
        split_store(smb, H1_HI, H1_LO, r1, c, ftanh(acc[p][2] + b0), ftanh(acc[p][3] + b1));
    }
    CPA_WAIT0(); __syncthreads();

    // ==== L2: h2 = tanh(h1 @ W_h1 + b_h1) ====
    GEMM(1, 4, H1_HI, H1_LO);
    stageB_async(smb, g_B[2][0]);
#pragma unroll
    for (int p = 0; p < 16; p++) {
        int c = p * 8 + qi * 2;
        float b0 = __ldg(b_h1 + c), b1 = __ldg(b_h1 + c + 1);
        split_store(smb, H2_HI, H2_LO, r0, c, ftanh(acc[p][0] + b0), ftanh(acc[p][1] + b1));
        split_store(smb, H2_HI, H2_LO, r1, c, ftanh(acc[p][2] + b0), ftanh(acc[p][3] + b1));
    }
    CPA_WAIT0(); __syncthreads();

    // ==== L3: h3 in regs; f per-row; g3 -> X ====
    GEMM(2, 4, H2_HI, H2_LO);
    stageB_async(smb, g_B[3][0]);
    {
        float pf0[3] = {0, 0, 0}, pf1[3] = {0, 0, 0};
#pragma unroll
        for (int p = 0; p < 16; p++) {
            int c = p * 8 + qi * 2;
            float b0 = __ldg(b_h2 + c), b1 = __ldg(b_h2 + c + 1);
            float h00 = ftanh(acc[p][0] + b0), h01 = ftanh(acc[p][1] + b1);
            float h10 = ftanh(acc[p][2] + b0), h11 = ftanh(acc[p][3] + b1);
            float wa0 = __ldg(W_out + c * 3 + 0), wa1 = __ldg(W_out + c * 3 + 1),
                  wa2 = __ldg(W_out + c * 3 + 2);
            float wb0 = __ldg(W_out + c * 3 + 3), wb1 = __ldg(W_out + c * 3 + 4),
                  wb2 = __ldg(W_out + c * 3 + 5);
            pf0[0] += h00 * wa0 + h01 * wb0;
            pf0[1] += h00 * wa1 + h01 * wb1;
            pf0[2] += h00 * wa2 + h01 * wb2;
            pf1[0] += h10 * wa0 + h11 * wb0;
            pf1[1] += h10 * wa1 + h11 * wb1;
            pf1[2] += h10 * wa2 + h11 * wb2;
            float s0a = ep0[0] * wa0 + ep0[1] * wa1 + ep0[2] * wa2;
            float s0b = ep0[0] * wb0 + ep0[1] * wb1 + ep0[2] * wb2;
            float s1a = ep1[0] * wa0 + ep1[1] * wa1 + ep1[2] * wa2;
            float s1b = ep1[0] * wb0 + ep1[1] * wb1 + ep1[2] * wb2;
            split_store(smb, X_HI, X_LO, r0, c,
                        s0a * oscale * (1.0f - h00 * h00),
                        s0b * oscale * (1.0f - h01 * h01));
            split_store(smb, X_HI, X_LO, r1, c,
                        s1a * oscale * (1.0f - h10 * h10),
                        s1b * oscale * (1.0f - h11 * h11));
        }
#pragma unroll
        for (int d = 0; d < 3; d++) {
            pf0[d] += __shfl_down_sync(0xffffffffu, pf0[d], 2, 4);
            pf0[d] += __shfl_down_sync(0xffffffffu, pf0[d], 1, 4);
            pf1[d] += __shfl_down_sync(0xffffffffu, pf1[d], 2, 4);
            pf1[d] += __shfl_down_sync(0xffffffffu, pf1[d], 1, 4);
        }
        if (qi == 0) {
#pragma unroll
            for (int d = 0; d < 3; d++) {
                if (grow0 < BTOT) out[grow0 * NDIM + d] = (pf0[d] + __ldg(b_out + d)) * oscale;
                if (grow1 < BTOT) out[grow1 * NDIM + d] = (pf1[d] + __ldg(b_out + d)) * oscale;
            }
        }
    }
    CPA_WAIT0(); __syncthreads();

    // ==== g2 = (g3 @ W_h2) * (1 - h2^2) -> X ====
    GEMM(3, 4, X_HI, X_LO);
    stageB_async(smb, g_B[4][0]);
#pragma unroll
    for (int p = 0; p < 16; p++) {
        int c = p * 8 + qi * 2;
        float h00, h01, h10, h11;
        ld_pair(smb, H2_HI, H2_LO, r0, c, h00, h01);
        ld_pair(smb, H2_HI, H2_LO, r1, c, h10, h11);
        split_store(smb, X_HI, X_LO, r0, c,
                    acc[p][0] * (1.0f - h00 * h00), acc[p][1] * (1.0f - h01 * h01));
        split_store(smb, X_HI, X_LO, r1, c,
                    acc[p][2] * (1.0f - h10 * h10), acc[p][3] * (1.0f - h11 * h11));
    }
    CPA_WAIT0(); __syncthreads();

    // ==== g1 = (g2 @ W_h1) * (1 - h1^2); gz; neg_div ====
    GEMM(4, 4, X_HI, X_LO);
    {
        float gz0[3] = {0, 0, 0}, gz1[3] = {0, 0, 0};
#pragma unroll
        for (int p = 0; p < 16; p++) {
            int c = p * 8 + qi * 2;
            float h00, h01, h10, h11;
            ld_pair(smb, H1_HI, H1_LO, r0, c, h00, h01);
            ld_pair(smb, H1_HI, H1_LO, r1, c, h10, h11);
            float g00 = acc[p][0] * (1.0f - h00 * h00);
            float g01 = acc[p][1] * (1.0f - h01 * h01);
            float g10 = acc[p][2] * (1.0f - h10 * h10);
            float g11 = acc[p][3] * (1.0f - h11 * h11);
#pragma unroll
            for (int d = 0; d < 3; d++) {
                float w0 = __ldg(W_in + d * NHID + c);
                float w1 = __ldg(W_in + d * NHID + c + 1);
                gz0[d] += g00 * w0 + g01 * w1;
                gz1[d] += g10 * w0 + g11 * w1;
            }
        }
#pragma unroll
        for (int d = 0; d < 3; d++) {
            gz0[d] += __shfl_down_sync(0xffffffffu, gz0[d], 2, 4);
            gz0[d] += __shfl_down_sync(0xffffffffu, gz0[d], 1, 4);
            gz1[d] += __shfl_down_sync(0xffffffffu, gz1[d], 2, 4);
            gz1[d] += __shfl_down_sync(0xffffffffu, gz1[d], 1, 4);
        }
        if (qi == 0) {
            if (grow0 < BTOT)
                out[BTOT * NDIM + grow0] = -(gz0[0] * ep0[0] + gz0[1] * ep0[1] + gz0[2] * ep0[2]);
            if (grow1 < BTOT)
                out[BTOT * NDIM + grow1] = -(gz1[0] * ep1[0] + gz1[1] * ep1[1] + gz1[2] * ep1[2]);
        }
    }
}

extern "C" void kernel_launch(void* const* d_in, const int* in_sizes, int n_in,
                              void* d_out, int out_size) {
    const float* t_p     = (const float*)d_in[0];
    const float* z       = (const float*)d_in[1];
    const float* context = (const float*)d_in[3];
    const float* eps     = (const float*)d_in[4];
    const float* W_in    = (const float*)d_in[5];
    const float* b_in    = (const float*)d_in[6];
    const float* W_h1    = (const float*)d_in[7];
    const float* b_h1    = (const float*)d_in[8];
    const float* W_h2    = (const float*)d_in[9];
    const float* b_h2    = (const float*)d_in[10];
    const float* W_out   = (const float*)d_in[11];
    const float* b_out   = (const float*)d_in[12];
    const float* scale_p = (const float*)d_in[13];
    float* out = (float*)d_out;

    cudaFuncSetAttribute(ode_mma, cudaFuncAttributeMaxDynamicSharedMemorySize, SM_TOT);

    prep_k<<<(5 * NHID * NHID + 255) / 256, 256>>>(W_in, W_h1, W_h2);

    const int grid = (BTOT + TILE - 1) / TILE;   // 7813
    ode_mma<<<grid, NT, SM_TOT>>>(t_p, z, context, eps,
                                  W_in, b_in, b_h1, b_h2,
                                  W_out, b_out, scale_p, out);
}

// round 17
// speedup vs baseline: 5.4011x; 1.0809x over previous
#include <cuda_runtime.h>
#include <cuda_fp16.h>
#include <cstdint>

#define BTOT   500000
#define NDIM   3
#define NCOND  64
#define NHID   128
#define NIN    68
#define TILE   64
#define NT     128

// SMEM slots (bytes). 5 activation slots + one full 32KB B slot = 112 KB.
#define S0     0          // in_hi -> g3_hi -> g2_hi
#define S1     16384      // in_lo -> mask2 (fp16)
#define S2     32768      // h1_hi
#define S3     49152      // h1_lo
#define S4     65536      // h2_hi(single) -> g3_lo -> g2_lo
#define B_SL   81920      // 32KB full B tile
#define SM_TOT 114688

// Pre-swizzled fp16 weight operands (full-K layout):
// 0=W_in^T(padK, rows permuted z,z,z,t,ctx) 1=W_h1^T 2=W_h2^T 3=W_h2 4=W_h1
__device__ __align__(16) unsigned char g_B[5][32768];

// Full-K layout: row stride 256B (128 fp16), 16B chunks, 16-chunk XOR swizzle.
__device__ __forceinline__ int swoff(int r, int k) {
    return r * 256 + ((((k >> 3) ^ (r & 7)) & 15) << 4) + (k & 7) * 2;
}
__device__ __forceinline__ uint32_t swbase(int r, int kb) {
    return (uint32_t)(r * 256 + ((((kb >> 3) ^ (r & 7)) & 15) << 4));
}

__global__ void prep_k(const float* __restrict__ Wi, const float* __restrict__ W1,
                       const float* __restrict__ W2) {
    int idx = blockIdx.x * blockDim.x + threadIdx.x;
    if (idx >= 5 * NHID * NHID) return;
    int t = idx >> 14, e = idx & 16383, n = e >> 7, k = e & 127;
    float v;
    switch (t) {
        case 0: {   // fwd L1, input rows permuted: 0..2=z, 3=t(orig 67), 4..67=ctx(k-1)
            if (k < NIN) {
                int kk = (k < 3) ? k : (k == 3 ? 67 : k - 1);
                v = Wi[kk * NHID + n];
            } else v = 0.0f;
            break;
        }
        case 1:  v = W1[k * NHID + n]; break;                     // fwd L2
        case 2:  v = W2[k * NHID + n]; break;                     // fwd L3
        case 3:  v = W2[n * NHID + k]; break;                     // bwd g2
        default: v = W1[n * NHID + k]; break;                     // bwd g1
    }
    *(unsigned short*)(g_B[t] + swoff(n, k)) = __half_as_ushort(__float2half_rn(v));
}

// Batched tanh pair: one rcp for two values. tanh(x) = 1 - 2/(e^{2x}+1).
__device__ __forceinline__ void ftanh2(float x0, float x1, float& h0, float& h1) {
    float e0 = __expf(2.0f * x0), e1 = __expf(2.0f * x1);
    float p0 = e0 + 1.0f, p1 = e1 + 1.0f;
    float r;
    asm("rcp.approx.f32 %0, %1;" : "=f"(r) : "f"(p0 * p1));
    h0 = fmaf(-2.0f * p1, r, 1.0f);
    h1 = fmaf(-2.0f * p0, r, 1.0f);
}

__device__ __forceinline__ void ldsm4(uint32_t a[4], uint32_t addr) {
    asm volatile("ldmatrix.sync.aligned.m8n8.x4.shared.b16 {%0,%1,%2,%3}, [%4];"
        : "=r"(a[0]), "=r"(a[1]), "=r"(a[2]), "=r"(a[3]) : "r"(addr));
}
__device__ __forceinline__ void mma16816(float d[4], const uint32_t a[4],
                                         uint32_t b0, uint32_t b1) {
    asm volatile("mma.sync.aligned.m16n8k16.row.col.f32.f16.f16.f32 "
        "{%0,%1,%2,%3}, {%4,%5,%6,%7}, {%8,%9}, {%0,%1,%2,%3};"
        : "+f"(d[0]), "+f"(d[1]), "+f"(d[2]), "+f"(d[3])
        : "r"(a[0]), "r"(a[1]), "r"(a[2]), "r"(a[3]), "r"(b0), "r"(b1));
}

__device__ __forceinline__ void split_store(unsigned char* smb, int hiB, int loB,
                                            int r, int c, float v0, float v1) {
    __half2 h = __floats2half2_rn(v0, v1);
    float2 hf = __half22float2(h);
    __half2 l = __floats2half2_rn(v0 - hf.x, v1 - hf.y);
    int o = swoff(r, c);
    *(__half2*)(smb + hiB + o) = h;
    *(__half2*)(smb + loB + o) = l;
}
__device__ __forceinline__ void single_store(unsigned char* smb, int off,
                                             int r, int c, float v0, float v1) {
    *(__half2*)(smb + off + swoff(r, c)) = __floats2half2_rn(v0, v1);
}
__device__ __forceinline__ void ld_pair(const unsigned char* smb, int hiB, int loB,
                                        int r, int c, float& v0, float& v1) {
    int o = swoff(r, c);
    float2 fh = __half22float2(*(const __half2*)(smb + hiB + o));
    float2 fl = __half22float2(*(const __half2*)(smb + loB + o));
    v0 = fh.x + fl.x;
    v1 = fh.y + fl.y;
}
__device__ __forceinline__ void ld_single(const unsigned char* smb, int off,
                                          int r, int c, float& v0, float& v1) {
    float2 f = __half22float2(*(const __half2*)(smb + off + swoff(r, c)));
    v0 = f.x; v1 = f.y;
}

__device__ __forceinline__ void stageB_async(unsigned char* smb, const unsigned char* src) {
    uint32_t s = (uint32_t)__cvta_generic_to_shared(smb + B_SL);
    for (int i = threadIdx.x; i < 2048; i += NT)
        asm volatile("cp.async.cg.shared.global [%0], [%1], 16;"
                     :: "r"(s + i * 16), "l"(src + i * 16));
    asm volatile("cp.async.commit_group;");
}
#define CPA_WAIT0() asm volatile("cp.async.wait_group 0;")

// Full-K sweep. TERMS=2: acc = Ahi*B + Alo*B ; TERMS=1: acc = Ahi*B.
template<int N_KS, int TERMS>
__device__ __forceinline__ void sweep(uint32_t aHiU, uint32_t aLoU, uint32_t bU,
                                      int a_r, int a_kadd, int b_radd, int b_kadd,
                                      float acc[16][4]) {
#pragma unroll
    for (int p = 0; p < 16; p++)
#pragma unroll
        for (int q = 0; q < 4; q++) acc[p][q] = 0.0f;
#pragma unroll
    for (int i = 0; i < N_KS; i++) {
        uint32_t ahi[4], alo[4];
        ldsm4(ahi, aHiU + swbase(a_r, i * 16 + a_kadd));
        if (TERMS == 2) ldsm4(alo, aLoU + swbase(a_r, i * 16 + a_kadd));
#pragma unroll
        for (int p = 0; p < 8; p++) {
            uint32_t b[4];
            ldsm4(b, bU + swbase(p * 16 + b_radd, i * 16 + b_kadd));
            mma16816(acc[2 * p],     ahi, b[0], b[1]);
            mma16816(acc[2 * p + 1], ahi, b[2], b[3]);
            if (TERMS == 2) {
                mma16816(acc[2 * p],     alo, b[0], b[1]);
                mma16816(acc[2 * p + 1], alo, b[2], b[3]);
            }
        }
    }
}

__global__ __launch_bounds__(NT, 2)
void ode_mma(const float* __restrict__ t_p,
             const float* __restrict__ z,
             const float* __restrict__ context,
             const float* __restrict__ eps,
             const float* __restrict__ W_in, const float* __restrict__ b_in,
             const float* __restrict__ b_h1, const float* __restrict__ b_h2,
             const float* __restrict__ W_out, const float* __restrict__ b_out,
             const float* __restrict__ scale_p,
             float* __restrict__ out)
{
    extern __shared__ unsigned char smb[];
    uint32_t smu = (uint32_t)__cvta_generic_to_shared(smb);

    const int t    = threadIdx.x;
    const int warp = t >> 5;
    const int lane = t & 31;
    const int row0 = blockIdx.x * TILE;
    const float tval   = *t_p;
    const float oscale = *scale_p;

    const int sub = lane >> 3, ro = lane & 7;
    const int a_r    = warp * 16 + ((sub & 1) << 3) + ro;
    const int a_kadd = (sub >> 1) << 3;
    const int b_radd = ((sub >> 1) << 3) + ro;
    const int b_kadd = (sub & 1) << 3;

    const int g  = lane >> 2, qi = lane & 3;
    const int r0 = warp * 16 + g, r1 = r0 + 8;
    const int grow0 = row0 + r0, grow1 = row0 + r1;

    const uint32_t bU = smu + B_SL;

    // ---- prefetch B0; stage input (permuted: z,z,z,t,ctx) -> S0/S1 ----
    stageB_async(smb, g_B[0]);

    if (t < TILE) {
        int grow = row0 + t;
        float z0 = 0.0f, z1 = 0.0f, z2 = 0.0f;
        if (grow < BTOT) {
            z0 = z[grow * NDIM + 0];
            z1 = z[grow * NDIM + 1];
            z2 = z[grow * NDIM + 2];
        }
        split_store(smb, S0, S1, t, 0, z0, z1);
        split_store(smb, S0, S1, t, 2, z2, (grow < BTOT) ? tval : 0.0f);
    }
#pragma unroll
    for (int i = 0; i < 8; i++) {
        int fidx = t + i * NT;
        int r = fidx >> 4, c4 = fidx & 15;
        int grow = row0 + r;
        float4 v = make_float4(0.0f, 0.0f, 0.0f, 0.0f);
        if (grow < BTOT)
            v = __ldg((const float4*)(context + grow * NCOND) + c4);
        int k = 4 + 4 * c4;
        split_store(smb, S0, S1, r, k,     v.x, v.y);
        split_store(smb, S0, S1, r, k + 2, v.z, v.w);
    }
#pragma unroll
    for (int i = 0; i < 3; i++) {   // zero pad k=68..79
        int idx = t + i * NT;
        int r = idx / 6, pr = idx - r * 6;
        split_store(smb, S0, S1, r, 68 + 2 * pr, 0.0f, 0.0f);
    }

    float ep0[3], ep1[3];
#pragma unroll
    for (int d = 0; d < 3; d++) {
        ep0[d] = (grow0 < BTOT) ? __ldg(eps + grow0 * NDIM + d) : 0.0f;
        ep1[d] = (grow1 < BTOT) ? __ldg(eps + grow1 * NDIM + d) : 0.0f;
    }

    // De-phase co-resident CTA pairs (first waves): odd CTAs skew half a phase.
    if ((blockIdx.x & 1) && blockIdx.x < 296) {
        long long t0 = clock64();
        while (clock64() - t0 < 4000) { }
    }
    CPA_WAIT0(); __syncthreads();

    float acc[16][4];

    // ==== L1: h1 = tanh(in @ W_in + b_in) -> S2,S3  (K=80: 5 ksteps) ====
    sweep<5, 2>(smu + S0, smu + S1, bU, a_r, a_kadd, b_radd, b_kadd, acc);
    __syncthreads();
    stageB_async(smb, g_B[1]);
#pragma unroll
    for (int p = 0; p < 16; p++) {
        int c = p * 8 + qi * 2;
        float b0 = __ldg(b_in + c), b1 = __ldg(b_in + c + 1);
        float h00, h01, h10, h11;
        ftanh2(acc[p][0] + b0, acc[p][1] + b1, h00, h01);
        ftanh2(acc[p][2] + b0, acc[p][3] + b1, h10, h11);
        split_store(smb, S2, S3, r0, c, h00, h01);
        split_store(smb, S2, S3, r1, c, h10, h11);
    }
    CPA_WAIT0(); __syncthreads();

    // ==== L2: h2 -> S4 (fp16 single); exact mask2=1-h2^2 -> S1 (fp16) ====
    sweep<8, 2>(smu + S2, smu + S3, bU, a_r, a_kadd, b_radd, b_kadd, acc);
    __syncthreads();
    stageB_async(smb, g_B[2]);
#pragma unroll
    for (int p = 0; p < 16; p++) {
        int c = p * 8 + qi * 2;
        float b0 = __ldg(b_h1 + c), b1 = __ldg(b_h1 + c + 1);
        float h00, h01, h10, h11;
        ftanh2(acc[p][0] + b0, acc[p][1] + b1, h00, h01);
        ftanh2(acc[p][2] + b0, acc[p][3] + b1, h10, h11);
        single_store(smb, S4, r0, c, h00, h01);
        single_store(smb, S4, r1, c, h10, h11);
        single_store(smb, S1, r0, c, 1.0f - h00 * h00, 1.0f - h01 * h01);
        single_store(smb, S1, r1, c, 1.0f - h10 * h10, 1.0f - h11 * h11);
    }
    CPA_WAIT0(); __syncthreads();

    // ==== L3 (A = h2 single-fp16): h3 in regs; f out; g3 -> S0(hi),S4(lo) ====
    sweep<8, 1>(smu + S4, smu + S4, bU, a_r, a_kadd, b_radd, b_kadd, acc);
    __syncthreads();
    stageB_async(smb, g_B[3]);
    {
        float pf0[3] = {0, 0, 0}, pf1[3] = {0, 0, 0};
#pragma unroll
        for (int p = 0; p < 16; p++) {
            int c = p * 8 + qi * 2;
            float b0 = __ldg(b_h2 + c), b1 = __ldg(b_h2 + c + 1);
            float h00, h01, h10, h11;
            ftanh2(acc[p][0] + b0, acc[p][1] + b1, h00, h01);
            ftanh2(acc[p][2] + b0, acc[p][3] + b1, h10, h11);
            float wa0 = __ldg(W_out + c * 3 + 0), wa1 = __ldg(W_out + c * 3 + 1),
                  wa2 = __ldg(W_out + c * 3 + 2);
            float wb0 = __ldg(W_out + c * 3 + 3), wb1 = __ldg(W_out + c * 3 + 4),
                  wb2 = __ldg(W_out + c * 3 + 5);
            pf0[0] += h00 * wa0 + h01 * wb0;
            pf0[1] += h00 * wa1 + h01 * wb1;
            pf0[2] += h00 * wa2 + h01 * wb2;
            pf1[0] += h10 * wa0 + h11 * wb0;
            pf1[1] += h10 * wa1 + h11 * wb1;
            pf1[2] += h10 * wa2 + h11 * wb2;
            float s0a = ep0[0] * wa0 + ep0[1] * wa1 + ep0[2] * wa2;
            float s0b = ep0[0] * wb0 + ep0[1] * wb1 + ep0[2] * wb2;
            float s1a = ep1[0] * wa0 + ep1[1] * wa1 + ep1[2] * wa2;
            float s1b = ep1[0] * wb0 + ep1[1] * wb1 + ep1[2] * wb2;
            split_store(smb, S0, S4, r0, c,
                        s0a * oscale * (1.0f - h00 * h00),
                        s0b * oscale * (1.0f - h01 * h01));
            split_store(smb, S0, S4, r1, c,
                        s1a * oscale * (1.0f - h10 * h10),
                        s1b * oscale * (1.0f - h11 * h11));
        }
#pragma unroll
        for (int d = 0; d < 3; d++) {
            pf0[d] += __shfl_down_sync(0xffffffffu, pf0[d], 2, 4);
            pf0[d] += __shfl_down_sync(0xffffffffu, pf0[d], 1, 4);
            pf1[d] += __shfl_down_sync(0xffffffffu, pf1[d], 2, 4);
            pf1[d] += __shfl_down_sync(0xffffffffu, pf1[d], 1, 4);
        }
        if (qi == 0) {
#pragma unroll
            for (int d = 0; d < 3; d++) {
                if (grow0 < BTOT) out[grow0 * NDIM + d] = (pf0[d] + __ldg(b_out + d)) * oscale;
                if (grow1 < BTOT) out[grow1 * NDIM + d] = (pf1[d] + __ldg(b_out + d)) * oscale;
            }
        }
    }
    CPA_WAIT0(); __syncthreads();

    // ==== g2 = (g3 @ W_h2) * mask2 -> S0,S4 in place ====
    sweep<8, 2>(smu + S0, smu + S4, bU, a_r, a_kadd, b_radd, b_kadd, acc);
    __syncthreads();
    stageB_async(smb, g_B[4]);
#pragma unroll
    for (int p = 0; p < 16; p++) {
        int c = p * 8 + qi * 2;
        float m00, m01, m10, m11;
        ld_single(smb, S1, r0, c, m00, m01);
        ld_single(smb, S1, r1, c, m10, m11);
        split_store(smb, S0, S4, r0, c, acc[p][0] * m00, acc[p][1] * m01);
        split_store(smb, S0, S4, r1, c, acc[p][2] * m10, acc[p][3] * m11);
    }
    CPA_WAIT0(); __syncthreads();

    // ==== g1 = (g2 @ W_h1) * (1 - h1^2); gz; neg_div ====
    sweep<8, 2>(smu + S0, smu + S4, bU, a_r, a_kadd, b_radd, b_kadd, acc);
    {
        float gz0[3] = {0, 0, 0}, gz1[3] = {0, 0, 0};
#pragma unroll
        for (int p = 0; p < 16; p++) {
            int c = p * 8 + qi * 2;
            float h00, h01, h10, h11;
            ld_pair(smb, S2, S3, r0, c, h00, h01);
            ld_pair(smb, S2, S3, r1, c, h10, h11);
            float g00 = acc[p][0] * (1.0f - h00 * h00);
            float g01 = acc[p][1] * (1.0f - h01 * h01);
            float g10 = acc[p][2] * (1.0f - h10 * h10);
            float g11 = acc[p][3] * (1.0f - h11 * h11);
#pragma unroll
            for (int d = 0; d < 3; d++) {
                float w0 = __ldg(W_in + d * NHID + c);
                float w1 = __ldg(W_in + d * NHID + c + 1);
                gz0[d] += g00 * w0 + g01 * w1;
                gz1[d] += g10 * w0 + g11 * w1;
            }
        }
#pragma unroll
        for (int d = 0; d < 3; d++) {
            gz0[d] += __shfl_down_sync(0xffffffffu, gz0[d], 2, 4);
            gz0[d] += __shfl_down_sync(0xffffffffu, gz0[d], 1, 4);
            gz1[d] += __shfl_down_sync(0xffffffffu, gz1[d], 2, 4);
            gz1[d] += __shfl_down_sync(0xffffffffu, gz1[d], 1, 4);
        }
        if (qi == 0) {
            if (grow0 < BTOT)
                out[BTOT * NDIM + grow0] = -(gz0[0] * ep0[0] + gz0[1] * ep0[1] + gz0[2] * ep0[2]);
            if (grow1 < BTOT)
                out[BTOT * NDIM + grow1] = -(gz1[0] * ep1[0] + gz1[1] * ep1[1] + gz1[2] * ep1[2]);
        }
    }
}

extern "C" void kernel_launch(void* const* d_in, const int* in_sizes, int n_in,
                              void* d_out, int out_size) {
    const float* t_p     = (const float*)d_in[0];
    const float* z       = (const float*)d_in[1];
    const float* context = (const float*)d_in[3];
    const float* eps     = (const float*)d_in[4];
    const float* W_in    = (const float*)d_in[5];
    const float* b_in    = (const float*)d_in[6];
    const float* W_h1    = (const float*)d_in[7];
    const float* b_h1    = (const float*)d_in[8];
    const float* W_h2    = (const float*)d_in[9];
    const float* b_h2    = (const float*)d_in[10];
    const float* W_out   = (const float*)d_in[11];
    const float* b_out   = (const float*)d_in[12];
    const float* scale_p = (const float*)d_in[13];
    float* out = (float*)d_out;

    cudaFuncSetAttribute(ode_mma, cudaFuncAttributeMaxDynamicSharedMemorySize, SM_TOT);

    prep_k<<<(5 * NHID * NHID + 255) / 256, 256>>>(W_in, W_h1, W_h2);

    const int grid = (BTOT + TILE - 1) / TILE;   // 7813
    ode_mma<<<grid, NT, SM_TOT>>>(t_p, z, context, eps,
                                  W_in, b_in, b_h1, b_h2,
                                  W_out, b_out, scale_p, out);
}